// round 6
// baseline (speedup 1.0000x reference)
#include <cuda_runtime.h>
#include <cstdint>

#define Bn   4
#define Tn   2048
#define Cn   1024
#define Hn   16
#define HSn  64
#define Mtot (Bn * Tn)   // 8192

// Scratch (static device globals: allocation-free, graph-capturable)
__device__ float g_q[Bn * Hn * Tn * HSn];
__device__ float g_k[Bn * Hn * Tn * HSn];
__device__ float g_v[Bn * Hn * Tn * HSn];
__device__ float g_att[Bn * Tn * Cn];

// ---------------------------------------------------------------------------
// Kernel 1: fused QKV projection
//   q[b,h,t,d] = sum_c x[b,t,c] * Wq[h,c,d]   (same for k,v)
// GEMM: A = x [8192 x 1024], B[k][n] = W[n/64, k, n%64], tile 128x128x16
// ---------------------------------------------------------------------------
__global__ __launch_bounds__(256) void qkv_kernel(
    const float* __restrict__ x,
    const float* __restrict__ Wq,
    const float* __restrict__ Wk,
    const float* __restrict__ Wv)
{
    __shared__ float As[16][128];
    __shared__ float Bs[16][128];

    const int tid   = threadIdx.x;
    const int mbase = blockIdx.x * 128;
    const int nbase = blockIdx.y * 128;

    const float* W   = (blockIdx.z == 0) ? Wq : (blockIdx.z == 1) ? Wk : Wv;
    float*       dst = (blockIdx.z == 0) ? g_q : (blockIdx.z == 1) ? g_k : g_v;

    const int tx = tid & 15;   // n direction
    const int ty = tid >> 4;   // m direction

    float acc[8][8];
#pragma unroll
    for (int i = 0; i < 8; ++i)
#pragma unroll
        for (int j = 0; j < 8; ++j) acc[i][j] = 0.f;

    for (int k0 = 0; k0 < Cn; k0 += 16) {
        __syncthreads();
#pragma unroll
        for (int l = 0; l < 2; ++l) {
            int e  = tid + l * 256;
            // A tile: 128 rows x 16 cols
            int ar = e >> 2;
            int ac = (e & 3) * 4;
            float4 av = *(const float4*)&x[(size_t)(mbase + ar) * Cn + k0 + ac];
            As[ac + 0][ar] = av.x; As[ac + 1][ar] = av.y;
            As[ac + 2][ar] = av.z; As[ac + 3][ar] = av.w;
            // B tile: 16 rows (k) x 128 cols (n)
            int br = e >> 5;
            int bn = (e & 31) * 4;
            int n  = nbase + bn;
            int h  = n >> 6;
            int d  = n & 63;
            float4 bv = *(const float4*)&W[(size_t)h * (Cn * HSn) + (size_t)(k0 + br) * HSn + d];
            *(float4*)&Bs[br][bn] = bv;
        }
        __syncthreads();
#pragma unroll
        for (int kk = 0; kk < 16; ++kk) {
            float a[8], b[8];
            *(float4*)&a[0] = *(float4*)&As[kk][ty * 8];
            *(float4*)&a[4] = *(float4*)&As[kk][ty * 8 + 4];
            *(float4*)&b[0] = *(float4*)&Bs[kk][tx * 8];
            *(float4*)&b[4] = *(float4*)&Bs[kk][tx * 8 + 4];
#pragma unroll
            for (int i = 0; i < 8; ++i)
#pragma unroll
                for (int j = 0; j < 8; ++j) acc[i][j] += a[i] * b[j];
        }
    }

    // scatter to [B,H,T,HS]
    const int n0 = nbase + tx * 8;
    const int h  = n0 >> 6;
    const int d0 = n0 & 63;
#pragma unroll
    for (int i = 0; i < 8; ++i) {
        int m = mbase + ty * 8 + i;
        int b = m >> 11;           // / Tn
        int t = m & (Tn - 1);
        float* p = &dst[(((size_t)(b * Hn + h)) * Tn + t) * HSn + d0];
        *(float4*)&p[0] = make_float4(acc[i][0], acc[i][1], acc[i][2], acc[i][3]);
        *(float4*)&p[4] = make_float4(acc[i][4], acc[i][5], acc[i][6], acc[i][7]);
    }
}

// ---------------------------------------------------------------------------
// Kernel 2: causal flash attention, fp32
// block = 256 threads = 128 query rows x 2 threads (each owns 32 of 64 dims)
// key tiles of 64 in smem; scores staged in padded smem; online softmax.
// ---------------------------------------------------------------------------
#define SMEM_ATTN ((64 * 64 * 2 + 128 * 65) * 4)

__global__ __launch_bounds__(256) void attn_kernel()
{
    extern __shared__ float sm[];
    float* Ks = sm;                 // [64][64]
    float* Vs = sm + 64 * 64;       // [64][64]
    float* Ss = sm + 2 * 64 * 64;   // [128][65] padded

    const int tid  = threadIdx.x;
    const int row  = tid >> 1;
    const int half = tid & 1;
    const int qt   = blockIdx.x;    // 0..15
    const int bh   = blockIdx.y;    // 0..63
    const int qrow = qt * 128 + row;

    const float* Kbase = g_k + (size_t)bh * Tn * HSn;
    const float* Vbase = g_v + (size_t)bh * Tn * HSn;
    const float* Qp    = g_q + (size_t)bh * Tn * HSn + (size_t)qrow * HSn + half * 32;

    float q[32];
#pragma unroll
    for (int i = 0; i < 32; i += 4) *(float4*)&q[i] = *(const float4*)&Qp[i];

    float acc[32];
#pragma unroll
    for (int i = 0; i < 32; ++i) acc[i] = 0.f;
    float mrun = -1e30f;
    float lsum = 0.f;

    // highest query row covered by this thread's warp (warp-uniform causal guard)
    const int warp_qmax = qt * 128 + (((tid & ~31) >> 1) | 15);

    const int nkt = qt * 2 + 2;
    for (int kt = 0; kt < nkt; ++kt) {
        __syncthreads();
#pragma unroll
        for (int e = 0; e < 4; ++e) {
            int idx = tid + e * 256;
            int r = idx >> 4;
            int c = (idx & 15) * 4;
            *(float4*)&Ks[r * 64 + c] = *(const float4*)&Kbase[(size_t)(kt * 64 + r) * 64 + c];
            *(float4*)&Vs[r * 64 + c] = *(const float4*)&Vbase[(size_t)(kt * 64 + r) * 64 + c];
        }
        __syncthreads();

        if (kt * 64 <= warp_qmax) {   // warp-uniform: safe for shfl_sync
            const int kbase = kt * 64;
            float mt = mrun;
#pragma unroll 4
            for (int j = 0; j < 64; ++j) {
                const float* kr = &Ks[j * 64 + half * 32];
                float part = 0.f;
#pragma unroll
                for (int i = 0; i < 32; i += 4) {
                    float4 kv = *(const float4*)&kr[i];
                    part += q[i] * kv.x + q[i + 1] * kv.y + q[i + 2] * kv.z + q[i + 3] * kv.w;
                }
                float s = (part + __shfl_xor_sync(0xffffffffu, part, 1)) * 0.125f;
                if (kbase + j > qrow) s = -1e30f;   // causal mask
                mt = fmaxf(mt, s);
                if (half == 0) Ss[row * 65 + j] = s;
            }
            __syncwarp();

            float corr = __expf(mrun - mt);
            lsum *= corr;
#pragma unroll
            for (int i = 0; i < 32; ++i) acc[i] *= corr;

#pragma unroll 4
            for (int j = 0; j < 64; ++j) {
                float p = __expf(Ss[row * 65 + j] - mt);
                lsum += p;
                const float* vr = &Vs[j * 64 + half * 32];
#pragma unroll
                for (int i = 0; i < 32; i += 4) {
                    float4 vv = *(const float4*)&vr[i];
                    acc[i]     += p * vv.x;
                    acc[i + 1] += p * vv.y;
                    acc[i + 2] += p * vv.z;
                    acc[i + 3] += p * vv.w;
                }
            }
            mrun = mt;
        }
    }

    // write concat-head layout [B,T,C]
    const int b = bh >> 4;
    const int h = bh & 15;
    const float inv = 1.0f / lsum;
    float* op = &g_att[((size_t)(b * Tn + qrow)) * Cn + h * 64 + half * 32];
#pragma unroll
    for (int i = 0; i < 32; i += 4) {
        *(float4*)&op[i] = make_float4(acc[i] * inv, acc[i + 1] * inv,
                                       acc[i + 2] * inv, acc[i + 3] * inv);
    }
}

// ---------------------------------------------------------------------------
// Kernel 3: output projection  out = att @ Wo^T + bo
//   B[k][n] = Wo[n*C + k]
// ---------------------------------------------------------------------------
__global__ __launch_bounds__(256) void proj_kernel(
    const float* __restrict__ Wo,
    const float* __restrict__ bo,
    float* __restrict__ out)
{
    __shared__ float As[16][128];
    __shared__ float Bs[16][128];

    const int tid   = threadIdx.x;
    const int mbase = blockIdx.x * 128;
    const int nbase = blockIdx.y * 128;
    const int tx = tid & 15;
    const int ty = tid >> 4;

    float acc[8][8];
#pragma unroll
    for (int i = 0; i < 8; ++i)
#pragma unroll
        for (int j = 0; j < 8; ++j) acc[i][j] = 0.f;

    for (int k0 = 0; k0 < Cn; k0 += 16) {
        __syncthreads();
#pragma unroll
        for (int l = 0; l < 2; ++l) {
            int e  = tid + l * 256;
            int ar = e >> 2;
            int ac = (e & 3) * 4;
            float4 av = *(const float4*)&g_att[(size_t)(mbase + ar) * Cn + k0 + ac];
            As[ac + 0][ar] = av.x; As[ac + 1][ar] = av.y;
            As[ac + 2][ar] = av.z; As[ac + 3][ar] = av.w;
            // Wo^T tile: each float4 = 4 consecutive k for one n row
            int n_off = e >> 2;
            int part  = e & 3;
            float4 wv = *(const float4*)&Wo[(size_t)(nbase + n_off) * Cn + k0 + part * 4];
            Bs[part * 4 + 0][n_off] = wv.x;
            Bs[part * 4 + 1][n_off] = wv.y;
            Bs[part * 4 + 2][n_off] = wv.z;
            Bs[part * 4 + 3][n_off] = wv.w;
        }
        __syncthreads();
#pragma unroll
        for (int kk = 0; kk < 16; ++kk) {
            float a[8], b[8];
            *(float4*)&a[0] = *(float4*)&As[kk][ty * 8];
            *(float4*)&a[4] = *(float4*)&As[kk][ty * 8 + 4];
            *(float4*)&b[0] = *(float4*)&Bs[kk][tx * 8];
            *(float4*)&b[4] = *(float4*)&Bs[kk][tx * 8 + 4];
#pragma unroll
            for (int i = 0; i < 8; ++i)
#pragma unroll
                for (int j = 0; j < 8; ++j) acc[i][j] += a[i] * b[j];
        }
    }

    const int n0 = nbase + tx * 8;
    float4 bias0 = *(const float4*)&bo[n0];
    float4 bias1 = *(const float4*)&bo[n0 + 4];
#pragma unroll
    for (int i = 0; i < 8; ++i) {
        int m = mbase + ty * 8 + i;
        float* p = &out[(size_t)m * Cn + n0];
        *(float4*)&p[0] = make_float4(acc[i][0] + bias0.x, acc[i][1] + bias0.y,
                                      acc[i][2] + bias0.z, acc[i][3] + bias0.w);
        *(float4*)&p[4] = make_float4(acc[i][4] + bias1.x, acc[i][5] + bias1.y,
                                      acc[i][6] + bias1.z, acc[i][7] + bias1.w);
    }
}

// ---------------------------------------------------------------------------
extern "C" void kernel_launch(void* const* d_in, const int* in_sizes, int n_in,
                              void* d_out, int out_size)
{
    (void)in_sizes; (void)n_in; (void)out_size;
    const float* x  = (const float*)d_in[0];
    const float* Wq = (const float*)d_in[1];
    const float* Wk = (const float*)d_in[2];
    const float* Wv = (const float*)d_in[3];
    const float* Wo = (const float*)d_in[4];
    const float* bo = (const float*)d_in[5];
    float* out = (float*)d_out;

    cudaFuncSetAttribute(attn_kernel, cudaFuncAttributeMaxDynamicSharedMemorySize, SMEM_ATTN);

    qkv_kernel<<<dim3(Mtot / 128, Cn / 128, 3), 256>>>(x, Wq, Wk, Wv);
    attn_kernel<<<dim3(Tn / 128, Bn * Hn), 256, SMEM_ATTN>>>();
    proj_kernel<<<dim3(Mtot / 128, Cn / 128), 256>>>(Wo, bo, out);
}

// round 10
// speedup vs baseline: 1.3095x; 1.3095x over previous
#include <cuda_runtime.h>
#include <cstdint>

#define Bn   4
#define Tn   2048
#define Cn   1024
#define Hn   16
#define HSn  64
#define Mtot (Bn * Tn)   // 8192

// Scratch (static device globals: allocation-free, graph-capturable)
__device__ float g_q[Bn * Hn * Tn * HSn];
__device__ float g_k[Bn * Hn * Tn * HSn];
__device__ float g_v[Bn * Hn * Tn * HSn];
__device__ float g_att[Bn * Tn * Cn];

// ---------------------------------------------------------------------------
// Kernel 1: fused QKV projection (unchanged from passing R6 kernel)
// ---------------------------------------------------------------------------
__global__ __launch_bounds__(256) void qkv_kernel(
    const float* __restrict__ x,
    const float* __restrict__ Wq,
    const float* __restrict__ Wk,
    const float* __restrict__ Wv)
{
    __shared__ float As[16][128];
    __shared__ float Bs[16][128];

    const int tid   = threadIdx.x;
    const int mbase = blockIdx.x * 128;
    const int nbase = blockIdx.y * 128;

    const float* W   = (blockIdx.z == 0) ? Wq : (blockIdx.z == 1) ? Wk : Wv;
    float*       dst = (blockIdx.z == 0) ? g_q : (blockIdx.z == 1) ? g_k : g_v;

    const int tx = tid & 15;
    const int ty = tid >> 4;

    float acc[8][8];
#pragma unroll
    for (int i = 0; i < 8; ++i)
#pragma unroll
        for (int j = 0; j < 8; ++j) acc[i][j] = 0.f;

    for (int k0 = 0; k0 < Cn; k0 += 16) {
        __syncthreads();
#pragma unroll
        for (int l = 0; l < 2; ++l) {
            int e  = tid + l * 256;
            int ar = e >> 2;
            int ac = (e & 3) * 4;
            float4 av = *(const float4*)&x[(size_t)(mbase + ar) * Cn + k0 + ac];
            As[ac + 0][ar] = av.x; As[ac + 1][ar] = av.y;
            As[ac + 2][ar] = av.z; As[ac + 3][ar] = av.w;
            int br = e >> 5;
            int bn = (e & 31) * 4;
            int n  = nbase + bn;
            int h  = n >> 6;
            int d  = n & 63;
            float4 bv = *(const float4*)&W[(size_t)h * (Cn * HSn) + (size_t)(k0 + br) * HSn + d];
            *(float4*)&Bs[br][bn] = bv;
        }
        __syncthreads();
#pragma unroll
        for (int kk = 0; kk < 16; ++kk) {
            float a[8], b[8];
            *(float4*)&a[0] = *(float4*)&As[kk][ty * 8];
            *(float4*)&a[4] = *(float4*)&As[kk][ty * 8 + 4];
            *(float4*)&b[0] = *(float4*)&Bs[kk][tx * 8];
            *(float4*)&b[4] = *(float4*)&Bs[kk][tx * 8 + 4];
#pragma unroll
            for (int i = 0; i < 8; ++i)
#pragma unroll
                for (int j = 0; j < 8; ++j) acc[i][j] += a[i] * b[j];
        }
    }

    const int n0 = nbase + tx * 8;
    const int h  = n0 >> 6;
    const int d0 = n0 & 63;
#pragma unroll
    for (int i = 0; i < 8; ++i) {
        int m = mbase + ty * 8 + i;
        int b = m >> 11;
        int t = m & (Tn - 1);
        float* p = &dst[(((size_t)(b * Hn + h)) * Tn + t) * HSn + d0];
        *(float4*)&p[0] = make_float4(acc[i][0], acc[i][1], acc[i][2], acc[i][3]);
        *(float4*)&p[4] = make_float4(acc[i][4], acc[i][5], acc[i][6], acc[i][7]);
    }
}

// ---------------------------------------------------------------------------
// Kernel 2: causal flash attention, register-tiled GEMM formulation.
// 256 threads: ty=tid>>3 owns q-rows ty*4..+3 (both phases); tx=tid&7 is
// key-group (scores) / dim-group (PV). Per-thread 4x8 microtiles, online
// softmax with shfl_xor row reductions over the 8 tx lanes.
// Smem: Qs[64][128] (Q^T, pre-scaled), Ks[64][68] (K^T), Vs[64][68], Ps[128][68].
// ---------------------------------------------------------------------------
#define SMEM_ATTN ((64 * 128 + 64 * 68 + 64 * 68 + 128 * 68) * 4)   // 102400 B

__global__ __launch_bounds__(256) void attn_kernel()
{
    extern __shared__ float sm[];
    float* Qs = sm;                          // [64][128]  Qs[d*128+q]
    float* Ks = sm + 64 * 128;               // [64][68]   Ks[d*68+k]
    float* Vs = Ks + 64 * 68;                // [64][68]   Vs[k*68+d]
    float* Ps = Vs + 64 * 68;                // [128][68]  Ps[q*68+k]

    const int tid = threadIdx.x;
    const int ty  = tid >> 3;   // 0..31
    const int tx  = tid & 7;    // 0..7
    const int qt  = blockIdx.x; // 0..15
    const int bh  = blockIdx.y; // 0..63

    const float* Qb = g_q + (size_t)bh * Tn * HSn + (size_t)qt * 128 * HSn;
    const float* Kb = g_k + (size_t)bh * Tn * HSn;
    const float* Vb = g_v + (size_t)bh * Tn * HSn;

    // Load Q^T, pre-scaled by 1/sqrt(HS)=0.125. thread: row r, half d0.
    {
        const int r  = tid >> 1;
        const int d0 = (tid & 1) * 32;
        const float* qp = &Qb[(size_t)r * 64 + d0];
#pragma unroll
        for (int i = 0; i < 32; i += 4) {
            float4 v = *(const float4*)&qp[i];
            Qs[(d0 + i + 0) * 128 + r] = v.x * 0.125f;
            Qs[(d0 + i + 1) * 128 + r] = v.y * 0.125f;
            Qs[(d0 + i + 2) * 128 + r] = v.z * 0.125f;
            Qs[(d0 + i + 3) * 128 + r] = v.w * 0.125f;
        }
    }

    float m[4], l[4], o[4][8];
#pragma unroll
    for (int i = 0; i < 4; ++i) { m[i] = -1e30f; l[i] = 0.f; }
#pragma unroll
    for (int i = 0; i < 4; ++i)
#pragma unroll
        for (int j = 0; j < 8; ++j) o[i][j] = 0.f;

    const int nkt = qt * 2 + 2;
    for (int kt = 0; kt < nkt; ++kt) {
        __syncthreads();   // previous tile's K/V consumers done
        // Load K^T and V tiles: thread key=tid>>2 (0..63), d0=(tid&3)*16
        {
            const int key = tid >> 2;
            const int d0  = (tid & 3) * 16;
            const float* kr = &Kb[(size_t)(kt * 64 + key) * 64 + d0];
            const float* vr = &Vb[(size_t)(kt * 64 + key) * 64 + d0];
#pragma unroll
            for (int i = 0; i < 16; i += 4) {
                float4 kv = *(const float4*)&kr[i];
                Ks[(d0 + i + 0) * 68 + key] = kv.x;
                Ks[(d0 + i + 1) * 68 + key] = kv.y;
                Ks[(d0 + i + 2) * 68 + key] = kv.z;
                Ks[(d0 + i + 3) * 68 + key] = kv.w;
                *(float4*)&Vs[key * 68 + d0 + i] = *(const float4*)&vr[i];
            }
        }
        __syncthreads();

        // ---- score GEMM: s[4q][8k] ----
        float s[4][8];
#pragma unroll
        for (int i = 0; i < 4; ++i)
#pragma unroll
            for (int j = 0; j < 8; ++j) s[i][j] = 0.f;

#pragma unroll 4
        for (int d = 0; d < 64; ++d) {
            float a[4], b[8];
            *(float4*)&a[0] = *(float4*)&Qs[d * 128 + ty * 4];
            *(float4*)&b[0] = *(float4*)&Ks[d * 68 + tx * 8];
            *(float4*)&b[4] = *(float4*)&Ks[d * 68 + tx * 8 + 4];
#pragma unroll
            for (int i = 0; i < 4; ++i)
#pragma unroll
                for (int j = 0; j < 8; ++j) s[i][j] += a[i] * b[j];
        }

        // causal mask (only possible on the two diagonal tiles; uniform branch)
        if (kt >= 2 * qt) {
            const int krow0 = kt * 64 + tx * 8;
            const int qrow0 = qt * 128 + ty * 4;
#pragma unroll
            for (int i = 0; i < 4; ++i)
#pragma unroll
                for (int j = 0; j < 8; ++j)
                    if (krow0 + j > qrow0 + i) s[i][j] = -1e30f;
        }

        // ---- online softmax per row (reduce across 8 tx lanes) ----
#pragma unroll
        for (int i = 0; i < 4; ++i) {
            float mx = s[i][0];
#pragma unroll
            for (int j = 1; j < 8; ++j) mx = fmaxf(mx, s[i][j]);
            mx = fmaxf(mx, __shfl_xor_sync(0xffffffffu, mx, 1));
            mx = fmaxf(mx, __shfl_xor_sync(0xffffffffu, mx, 2));
            mx = fmaxf(mx, __shfl_xor_sync(0xffffffffu, mx, 4));
            const float mn = fmaxf(m[i], mx);
            const float sc = __expf(m[i] - mn);
            float ps = 0.f;
#pragma unroll
            for (int j = 0; j < 8; ++j) {
                s[i][j] = __expf(s[i][j] - mn);
                ps += s[i][j];
            }
            ps += __shfl_xor_sync(0xffffffffu, ps, 1);
            ps += __shfl_xor_sync(0xffffffffu, ps, 2);
            ps += __shfl_xor_sync(0xffffffffu, ps, 4);
            l[i] = l[i] * sc + ps;
            m[i] = mn;
#pragma unroll
            for (int j = 0; j < 8; ++j) o[i][j] *= sc;
        }

        // ---- write P (q-major, rows warp-private) ----
#pragma unroll
        for (int i = 0; i < 4; ++i) {
            float* pp = &Ps[(ty * 4 + i) * 68 + tx * 8];
            *(float4*)&pp[0] = make_float4(s[i][0], s[i][1], s[i][2], s[i][3]);
            *(float4*)&pp[4] = make_float4(s[i][4], s[i][5], s[i][6], s[i][7]);
        }
        __syncwarp();   // P rows for this ty are written by this warp only

        // ---- PV GEMM: o[4q][8d] += P[4q][64k] * V[64k][8d] ----
#pragma unroll 4
        for (int k = 0; k < 64; ++k) {
            float b[8];
            *(float4*)&b[0] = *(float4*)&Vs[k * 68 + tx * 8];
            *(float4*)&b[4] = *(float4*)&Vs[k * 68 + tx * 8 + 4];
#pragma unroll
            for (int i = 0; i < 4; ++i) {
                const float a = Ps[(ty * 4 + i) * 68 + k];
#pragma unroll
                for (int j = 0; j < 8; ++j) o[i][j] += a * b[j];
            }
        }
    }

    // epilogue: concat-head layout [B,T,C]
    const int b = bh >> 4;
    const int h = bh & 15;
#pragma unroll
    for (int i = 0; i < 4; ++i) {
        const int   row = qt * 128 + ty * 4 + i;
        const float inv = 1.0f / l[i];
        float* op = &g_att[((size_t)(b * Tn + row)) * Cn + h * 64 + tx * 8];
        *(float4*)&op[0] = make_float4(o[i][0] * inv, o[i][1] * inv,
                                       o[i][2] * inv, o[i][3] * inv);
        *(float4*)&op[4] = make_float4(o[i][4] * inv, o[i][5] * inv,
                                       o[i][6] * inv, o[i][7] * inv);
    }
}

// ---------------------------------------------------------------------------
// Kernel 3: output projection  out = att @ Wo^T + bo (unchanged from R6)
// ---------------------------------------------------------------------------
__global__ __launch_bounds__(256) void proj_kernel(
    const float* __restrict__ Wo,
    const float* __restrict__ bo,
    float* __restrict__ out)
{
    __shared__ float As[16][128];
    __shared__ float Bs[16][128];

    const int tid   = threadIdx.x;
    const int mbase = blockIdx.x * 128;
    const int nbase = blockIdx.y * 128;
    const int tx = tid & 15;
    const int ty = tid >> 4;

    float acc[8][8];
#pragma unroll
    for (int i = 0; i < 8; ++i)
#pragma unroll
        for (int j = 0; j < 8; ++j) acc[i][j] = 0.f;

    for (int k0 = 0; k0 < Cn; k0 += 16) {
        __syncthreads();
#pragma unroll
        for (int l = 0; l < 2; ++l) {
            int e  = tid + l * 256;
            int ar = e >> 2;
            int ac = (e & 3) * 4;
            float4 av = *(const float4*)&g_att[(size_t)(mbase + ar) * Cn + k0 + ac];
            As[ac + 0][ar] = av.x; As[ac + 1][ar] = av.y;
            As[ac + 2][ar] = av.z; As[ac + 3][ar] = av.w;
            int n_off = e >> 2;
            int part  = e & 3;
            float4 wv = *(const float4*)&Wo[(size_t)(nbase + n_off) * Cn + k0 + part * 4];
            Bs[part * 4 + 0][n_off] = wv.x;
            Bs[part * 4 + 1][n_off] = wv.y;
            Bs[part * 4 + 2][n_off] = wv.z;
            Bs[part * 4 + 3][n_off] = wv.w;
        }
        __syncthreads();
#pragma unroll
        for (int kk = 0; kk < 16; ++kk) {
            float a[8], b[8];
            *(float4*)&a[0] = *(float4*)&As[kk][ty * 8];
            *(float4*)&a[4] = *(float4*)&As[kk][ty * 8 + 4];
            *(float4*)&b[0] = *(float4*)&Bs[kk][tx * 8];
            *(float4*)&b[4] = *(float4*)&Bs[kk][tx * 8 + 4];
#pragma unroll
            for (int i = 0; i < 8; ++i)
#pragma unroll
                for (int j = 0; j < 8; ++j) acc[i][j] += a[i] * b[j];
        }
    }

    const int n0 = nbase + tx * 8;
    float4 bias0 = *(const float4*)&bo[n0];
    float4 bias1 = *(const float4*)&bo[n0 + 4];
#pragma unroll
    for (int i = 0; i < 8; ++i) {
        int m = mbase + ty * 8 + i;
        float* p = &out[(size_t)m * Cn + n0];
        *(float4*)&p[0] = make_float4(acc[i][0] + bias0.x, acc[i][1] + bias0.y,
                                      acc[i][2] + bias0.z, acc[i][3] + bias0.w);
        *(float4*)&p[4] = make_float4(acc[i][4] + bias1.x, acc[i][5] + bias1.y,
                                      acc[i][6] + bias1.z, acc[i][7] + bias1.w);
    }
}

// ---------------------------------------------------------------------------
extern "C" void kernel_launch(void* const* d_in, const int* in_sizes, int n_in,
                              void* d_out, int out_size)
{
    (void)in_sizes; (void)n_in; (void)out_size;
    const float* x  = (const float*)d_in[0];
    const float* Wq = (const float*)d_in[1];
    const float* Wk = (const float*)d_in[2];
    const float* Wv = (const float*)d_in[3];
    const float* Wo = (const float*)d_in[4];
    const float* bo = (const float*)d_in[5];
    float* out = (float*)d_out;

    cudaFuncSetAttribute(attn_kernel, cudaFuncAttributeMaxDynamicSharedMemorySize, SMEM_ATTN);

    qkv_kernel<<<dim3(Mtot / 128, Cn / 128, 3), 256>>>(x, Wq, Wk, Wv);
    attn_kernel<<<dim3(Tn / 128, Bn * Hn), 256, SMEM_ATTN>>>();
    proj_kernel<<<dim3(Mtot / 128, Cn / 128), 256>>>(Wo, bo, out);
}

// round 13
// speedup vs baseline: 1.8152x; 1.3862x over previous
#include <cuda_runtime.h>
#include <cuda_bf16.h>
#include <cstdint>

#define Bn   4
#define Tn   2048
#define Cn   1024
#define Hn   16
#define HSn  64
#define Mtot (Bn * Tn)   // 8192

// ---------------------------------------------------------------------------
// Scratch (static device globals: allocation-free, graph-capturable)
// ---------------------------------------------------------------------------
__device__ float g_q[Bn * Hn * Tn * HSn];
__device__ float g_k[Bn * Hn * Tn * HSn];
__device__ float g_v[Bn * Hn * Tn * HSn];
__device__ float g_att[Bn * Tn * Cn];

__device__ __nv_bfloat16 g_xhi[Mtot * Cn];
__device__ __nv_bfloat16 g_xlo[Mtot * Cn];
__device__ __nv_bfloat16 g_ahi[Mtot * Cn];
__device__ __nv_bfloat16 g_alo[Mtot * Cn];
__device__ __nv_bfloat16 g_wthi[3 * Cn * Cn];   // [3072][1024]  Wt[n][k]
__device__ __nv_bfloat16 g_wtlo[3 * Cn * Cn];
__device__ __nv_bfloat16 g_wohi[Cn * Cn];       // Wo[n][k] (n-major already)
__device__ __nv_bfloat16 g_wolo[Cn * Cn];

// ---------------------------------------------------------------------------
// Helpers (base-target legal: ldmatrix / mma.sync / cp.async only)
// ---------------------------------------------------------------------------
static __device__ __forceinline__ uint32_t smem_u32(const void* p) {
    uint32_t a;
    asm("{ .reg .u64 t; cvta.to.shared.u64 t, %1; cvt.u32.u64 %0, t; }"
        : "=r"(a) : "l"(p));
    return a;
}
static __device__ __forceinline__ void ldsm4(uint32_t* r, uint32_t addr) {
    asm volatile("ldmatrix.sync.aligned.m8n8.x4.shared.b16 {%0,%1,%2,%3}, [%4];"
                 : "=r"(r[0]), "=r"(r[1]), "=r"(r[2]), "=r"(r[3]) : "r"(addr));
}
static __device__ __forceinline__ void mma16816(float* d, const uint32_t* a,
                                                const uint32_t* b) {
    asm volatile(
        "mma.sync.aligned.m16n8k16.row.col.f32.bf16.bf16.f32 "
        "{%0,%1,%2,%3}, {%4,%5,%6,%7}, {%8,%9}, {%0,%1,%2,%3};"
        : "+f"(d[0]), "+f"(d[1]), "+f"(d[2]), "+f"(d[3])
        : "r"(a[0]), "r"(a[1]), "r"(a[2]), "r"(a[3]), "r"(b[0]), "r"(b[1]));
}

// ---------------------------------------------------------------------------
// Conversion kernels: fp32 -> bf16 hi/lo split
// ---------------------------------------------------------------------------
static __device__ __forceinline__ unsigned pack2(__nv_bfloat16 a, __nv_bfloat16 b) {
    return (unsigned)__bfloat16_as_ushort(b) << 16 | (unsigned)__bfloat16_as_ushort(a);
}

__global__ __launch_bounds__(256) void split_kernel(const float* __restrict__ src,
                                                    int n4, int mode)
{
    int i = blockIdx.x * 256 + threadIdx.x;
    if (i >= n4) return;
    const float* s = (mode == 1) ? g_att : src;
    __nv_bfloat16* hi = (mode == 0) ? g_xhi : (mode == 1) ? g_ahi : g_wohi;
    __nv_bfloat16* lo = (mode == 0) ? g_xlo : (mode == 1) ? g_alo : g_wolo;

    float4 v = ((const float4*)s)[i];
    __nv_bfloat16 h0 = __float2bfloat16(v.x);
    __nv_bfloat16 h1 = __float2bfloat16(v.y);
    __nv_bfloat16 h2 = __float2bfloat16(v.z);
    __nv_bfloat16 h3 = __float2bfloat16(v.w);
    __nv_bfloat16 l0 = __float2bfloat16(v.x - __bfloat162float(h0));
    __nv_bfloat16 l1 = __float2bfloat16(v.y - __bfloat162float(h1));
    __nv_bfloat16 l2 = __float2bfloat16(v.z - __bfloat162float(h2));
    __nv_bfloat16 l3 = __float2bfloat16(v.w - __bfloat162float(h3));

    uint2 uh; uh.x = pack2(h0, h1); uh.y = pack2(h2, h3);
    uint2 ul; ul.x = pack2(l0, l1); ul.y = pack2(l2, l3);
    *(uint2*)(hi + 4 * (size_t)i) = uh;
    *(uint2*)(lo + 4 * (size_t)i) = ul;
}

// Wq/Wk/Wv [h][c][d] -> Wt[n=(w*16+h)*64+d][k=c] bf16 hi/lo (smem transpose)
__global__ __launch_bounds__(256) void convw_kernel(const float* __restrict__ Wq,
                                                    const float* __restrict__ Wk,
                                                    const float* __restrict__ Wv)
{
    __shared__ float s[64][65];
    const int wh = blockIdx.x;
    const int c0 = blockIdx.y * 64;
    const int w  = wh >> 4;
    const int h  = wh & 15;
    const float* W = ((w == 0) ? Wq : (w == 1) ? Wk : Wv) + (size_t)h * Cn * HSn;
    const int tid = threadIdx.x;

#pragma unroll
    for (int i = 0; i < 16; ++i) {
        int idx = tid + i * 256;
        int r = idx >> 6, d = idx & 63;
        s[r][d] = W[(size_t)(c0 + r) * 64 + d];
    }
    __syncthreads();
#pragma unroll
    for (int i = 0; i < 16; ++i) {
        int idx = tid + i * 256;
        int dd = idx >> 6, cc = idx & 63;
        float v = s[cc][dd];
        __nv_bfloat16 hv = __float2bfloat16(v);
        __nv_bfloat16 lv = __float2bfloat16(v - __bfloat162float(hv));
        size_t o = (size_t)(wh * 64 + dd) * Cn + c0 + cc;
        g_wthi[o] = hv;
        g_wtlo[o] = lv;
    }
}

// ---------------------------------------------------------------------------
// mma.sync GEMM mainloop: C[128,128] = (Ah+Al)[128,1024] * (Bh+Bl)[128,1024]^T
// 8 warps (2m x 4n), 64x32 per warp. K-chunks of 32, cp.async double buffer.
// Smem tiles padded to stride 40 bf16 for ldmatrix.
// ---------------------------------------------------------------------------
#define KC      32
#define NKC     (Cn / KC)          // 32
#define LDSW    40                 // padded row stride (bf16)
#define TILE_B  (128 * LDSW * 2)   // 10240 B per operand-split tile
#define STAGE_B (4 * TILE_B)       // Ahi, Alo, Bhi, Blo
#define SMEM_GEMM (2 * STAGE_B)    // 81920 B

static __device__ __forceinline__ void issue_stage(
    uint32_t sb, int buf, int k0, int tid,
    const __nv_bfloat16* Ah, const __nv_bfloat16* Al,
    const __nv_bfloat16* Bh, const __nv_bfloat16* Bl)
{
    const __nv_bfloat16* srcs[4] = { Ah, Al, Bh, Bl };
#pragma unroll
    for (int q = 0; q < 4; ++q) {
#pragma unroll
        for (int l = 0; l < 2; ++l) {
            int t  = tid + l * 256;
            int r  = t >> 2;
            int c8 = (t & 3) * 8;
            uint32_t sa = sb + buf * STAGE_B + q * TILE_B + 2 * (r * LDSW + c8);
            const __nv_bfloat16* ga = srcs[q] + (size_t)r * Cn + k0 + c8;
            asm volatile("cp.async.cg.shared.global [%0], [%1], 16;"
                         :: "r"(sa), "l"(ga));
        }
    }
    asm volatile("cp.async.commit_group;" ::: "memory");
}

static __device__ __forceinline__ void gemm_mainloop(
    const __nv_bfloat16* Ah, const __nv_bfloat16* Al,
    const __nv_bfloat16* Bh, const __nv_bfloat16* Bl,
    char* smem, float acc[4][4][4])
{
    const int tid  = threadIdx.x;
    const int lane = tid & 31;
    const int warp = tid >> 5;
    const int wm   = (warp & 1) * 64;
    const int wn   = (warp >> 1) * 32;
    const uint32_t sb = smem_u32(smem);

    const int arow = lane & 15;
    const int acol = (lane >> 4) * 8;
    const int brow = (lane & 7) + 8 * (lane >> 4);
    const int bcol = 8 * ((lane >> 3) & 1);

#pragma unroll
    for (int mi = 0; mi < 4; ++mi)
#pragma unroll
        for (int ni = 0; ni < 4; ++ni)
#pragma unroll
            for (int e = 0; e < 4; ++e) acc[mi][ni][e] = 0.f;

    issue_stage(sb, 0, 0, tid, Ah, Al, Bh, Bl);

#pragma unroll 1
    for (int kc = 0; kc < NKC; ++kc) {
        const int cur = kc & 1;
        if (kc < NKC - 1) {
            issue_stage(sb, 1 - cur, (kc + 1) * KC, tid, Ah, Al, Bh, Bl);
            asm volatile("cp.async.wait_group 1;" ::: "memory");
        } else {
            asm volatile("cp.async.wait_group 0;" ::: "memory");
        }
        __syncthreads();

        const uint32_t abase = sb + cur * STAGE_B;
#pragma unroll
        for (int s = 0; s < 2; ++s) {
            const int k16 = s * 16;
            uint32_t ah[4][4], al[4][4];
#pragma unroll
            for (int mi = 0; mi < 4; ++mi) {
                uint32_t ra = abase + 2 * ((wm + mi * 16 + arow) * LDSW + k16 + acol);
                ldsm4(ah[mi], ra);
                ldsm4(al[mi], ra + TILE_B);
            }
            uint32_t bh[2][4], bl[2][4];
#pragma unroll
            for (int nb = 0; nb < 2; ++nb) {
                uint32_t rb = abase + 2 * TILE_B
                            + 2 * ((wn + nb * 16 + brow) * LDSW + k16 + bcol);
                ldsm4(bh[nb], rb);
                ldsm4(bl[nb], rb + TILE_B);
            }
#pragma unroll
            for (int mi = 0; mi < 4; ++mi)
#pragma unroll
                for (int ni = 0; ni < 4; ++ni) {
                    const uint32_t* bp  = &bh[ni >> 1][(ni & 1) * 2];
                    const uint32_t* blp = &bl[ni >> 1][(ni & 1) * 2];
                    mma16816(acc[mi][ni], ah[mi], bp);   // hi * hi
                    mma16816(acc[mi][ni], al[mi], bp);   // lo * hi
                    mma16816(acc[mi][ni], ah[mi], blp);  // hi * lo
                }
        }
        __syncthreads();
    }
}

// ---------------------------------------------------------------------------
// QKV GEMM (tensor path): grid (64, 24); epilogue scatters to [B,H,T,HS].
// ---------------------------------------------------------------------------
__global__ __launch_bounds__(256) void qkv_mma_kernel()
{
    extern __shared__ char smem[];
    const int mbase = blockIdx.x * 128;
    const int nglob = blockIdx.y * 128;

    float acc[4][4][4];
    gemm_mainloop(g_xhi + (size_t)mbase * Cn, g_xlo + (size_t)mbase * Cn,
                  g_wthi + (size_t)nglob * Cn, g_wtlo + (size_t)nglob * Cn,
                  smem, acc);

    const int lane = threadIdx.x & 31;
    const int warp = threadIdx.x >> 5;
    const int wm = (warp & 1) * 64;
    const int wn = (warp >> 1) * 32;
    const int g  = lane >> 2;
    const int tg = lane & 3;

    const int w = nglob >> 10;
    float* dst = (w == 0) ? g_q : (w == 1) ? g_k : g_v;

#pragma unroll
    for (int mi = 0; mi < 4; ++mi) {
        const int m0 = mbase + wm + mi * 16 + g;
        const int b  = m0 >> 11;
        const int t0 = m0 & (Tn - 1);
#pragma unroll
        for (int ni = 0; ni < 4; ++ni) {
            const int n = (nglob & 1023) + wn + ni * 8 + 2 * tg;
            const int h = n >> 6;
            const int d = n & 63;
            float* p0 = dst + (((size_t)(b * Hn + h)) * Tn + t0) * HSn + d;
            float* p1 = p0 + 8 * HSn;   // row m0+8, same b/h
            *(float2*)p0 = make_float2(acc[mi][ni][0], acc[mi][ni][1]);
            *(float2*)p1 = make_float2(acc[mi][ni][2], acc[mi][ni][3]);
        }
    }
}

// ---------------------------------------------------------------------------
// Output projection GEMM: out = att @ Wo^T + bo. grid (64, 8).
// ---------------------------------------------------------------------------
__global__ __launch_bounds__(256) void proj_mma_kernel(const float* __restrict__ bo,
                                                       float* __restrict__ out)
{
    extern __shared__ char smem[];
    const int mbase = blockIdx.x * 128;
    const int nbase = blockIdx.y * 128;

    float acc[4][4][4];
    gemm_mainloop(g_ahi + (size_t)mbase * Cn, g_alo + (size_t)mbase * Cn,
                  g_wohi + (size_t)nbase * Cn, g_wolo + (size_t)nbase * Cn,
                  smem, acc);

    const int lane = threadIdx.x & 31;
    const int warp = threadIdx.x >> 5;
    const int wm = (warp & 1) * 64;
    const int wn = (warp >> 1) * 32;
    const int g  = lane >> 2;
    const int tg = lane & 3;

#pragma unroll
    for (int mi = 0; mi < 4; ++mi) {
        const int m0 = mbase + wm + mi * 16 + g;
#pragma unroll
        for (int ni = 0; ni < 4; ++ni) {
            const int n = nbase + wn + ni * 8 + 2 * tg;
            const float bx = bo[n], by = bo[n + 1];
            float* p0 = out + (size_t)m0 * Cn + n;
            float* p1 = p0 + 8 * Cn;
            *(float2*)p0 = make_float2(acc[mi][ni][0] + bx, acc[mi][ni][1] + by);
            *(float2*)p1 = make_float2(acc[mi][ni][2] + bx, acc[mi][ni][3] + by);
        }
    }
}

// ---------------------------------------------------------------------------
// Causal flash attention, register-tiled fp32 (passing R9 version, unchanged)
// ---------------------------------------------------------------------------
#define SMEM_ATTN ((64 * 128 + 64 * 68 + 64 * 68 + 128 * 68) * 4)   // 102400 B

__global__ __launch_bounds__(256) void attn_kernel()
{
    extern __shared__ float sm[];
    float* Qs = sm;                          // [64][128]  Qs[d*128+q]
    float* Ks = sm + 64 * 128;               // [64][68]   Ks[d*68+k]
    float* Vs = Ks + 64 * 68;                // [64][68]   Vs[k*68+d]
    float* Ps = Vs + 64 * 68;                // [128][68]  Ps[q*68+k]

    const int tid = threadIdx.x;
    const int ty  = tid >> 3;
    const int tx  = tid & 7;
    const int qt  = blockIdx.x;
    const int bh  = blockIdx.y;

    const float* Qb = g_q + (size_t)bh * Tn * HSn + (size_t)qt * 128 * HSn;
    const float* Kb = g_k + (size_t)bh * Tn * HSn;
    const float* Vb = g_v + (size_t)bh * Tn * HSn;

    {
        const int r  = tid >> 1;
        const int d0 = (tid & 1) * 32;
        const float* qp = &Qb[(size_t)r * 64 + d0];
#pragma unroll
        for (int i = 0; i < 32; i += 4) {
            float4 v = *(const float4*)&qp[i];
            Qs[(d0 + i + 0) * 128 + r] = v.x * 0.125f;
            Qs[(d0 + i + 1) * 128 + r] = v.y * 0.125f;
            Qs[(d0 + i + 2) * 128 + r] = v.z * 0.125f;
            Qs[(d0 + i + 3) * 128 + r] = v.w * 0.125f;
        }
    }

    float m[4], l[4], o[4][8];
#pragma unroll
    for (int i = 0; i < 4; ++i) { m[i] = -1e30f; l[i] = 0.f; }
#pragma unroll
    for (int i = 0; i < 4; ++i)
#pragma unroll
        for (int j = 0; j < 8; ++j) o[i][j] = 0.f;

    const int nkt = qt * 2 + 2;
    for (int kt = 0; kt < nkt; ++kt) {
        __syncthreads();
        {
            const int key = tid >> 2;
            const int d0  = (tid & 3) * 16;
            const float* kr = &Kb[(size_t)(kt * 64 + key) * 64 + d0];
            const float* vr = &Vb[(size_t)(kt * 64 + key) * 64 + d0];
#pragma unroll
            for (int i = 0; i < 16; i += 4) {
                float4 kv = *(const float4*)&kr[i];
                Ks[(d0 + i + 0) * 68 + key] = kv.x;
                Ks[(d0 + i + 1) * 68 + key] = kv.y;
                Ks[(d0 + i + 2) * 68 + key] = kv.z;
                Ks[(d0 + i + 3) * 68 + key] = kv.w;
                *(float4*)&Vs[key * 68 + d0 + i] = *(const float4*)&vr[i];
            }
        }
        __syncthreads();

        float s[4][8];
#pragma unroll
        for (int i = 0; i < 4; ++i)
#pragma unroll
            for (int j = 0; j < 8; ++j) s[i][j] = 0.f;

#pragma unroll 4
        for (int d = 0; d < 64; ++d) {
            float a[4], b[8];
            *(float4*)&a[0] = *(float4*)&Qs[d * 128 + ty * 4];
            *(float4*)&b[0] = *(float4*)&Ks[d * 68 + tx * 8];
            *(float4*)&b[4] = *(float4*)&Ks[d * 68 + tx * 8 + 4];
#pragma unroll
            for (int i = 0; i < 4; ++i)
#pragma unroll
                for (int j = 0; j < 8; ++j) s[i][j] += a[i] * b[j];
        }

        if (kt >= 2 * qt) {
            const int krow0 = kt * 64 + tx * 8;
            const int qrow0 = qt * 128 + ty * 4;
#pragma unroll
            for (int i = 0; i < 4; ++i)
#pragma unroll
                for (int j = 0; j < 8; ++j)
                    if (krow0 + j > qrow0 + i) s[i][j] = -1e30f;
        }

#pragma unroll
        for (int i = 0; i < 4; ++i) {
            float mx = s[i][0];
#pragma unroll
            for (int j = 1; j < 8; ++j) mx = fmaxf(mx, s[i][j]);
            mx = fmaxf(mx, __shfl_xor_sync(0xffffffffu, mx, 1));
            mx = fmaxf(mx, __shfl_xor_sync(0xffffffffu, mx, 2));
            mx = fmaxf(mx, __shfl_xor_sync(0xffffffffu, mx, 4));
            const float mn = fmaxf(m[i], mx);
            const float sc = __expf(m[i] - mn);
            float ps = 0.f;
#pragma unroll
            for (int j = 0; j < 8; ++j) {
                s[i][j] = __expf(s[i][j] - mn);
                ps += s[i][j];
            }
            ps += __shfl_xor_sync(0xffffffffu, ps, 1);
            ps += __shfl_xor_sync(0xffffffffu, ps, 2);
            ps += __shfl_xor_sync(0xffffffffu, ps, 4);
            l[i] = l[i] * sc + ps;
            m[i] = mn;
#pragma unroll
            for (int j = 0; j < 8; ++j) o[i][j] *= sc;
        }

#pragma unroll
        for (int i = 0; i < 4; ++i) {
            float* pp = &Ps[(ty * 4 + i) * 68 + tx * 8];
            *(float4*)&pp[0] = make_float4(s[i][0], s[i][1], s[i][2], s[i][3]);
            *(float4*)&pp[4] = make_float4(s[i][4], s[i][5], s[i][6], s[i][7]);
        }
        __syncwarp();

#pragma unroll 4
        for (int k = 0; k < 64; ++k) {
            float b[8];
            *(float4*)&b[0] = *(float4*)&Vs[k * 68 + tx * 8];
            *(float4*)&b[4] = *(float4*)&Vs[k * 68 + tx * 8 + 4];
#pragma unroll
            for (int i = 0; i < 4; ++i) {
                const float a = Ps[(ty * 4 + i) * 68 + k];
#pragma unroll
                for (int j = 0; j < 8; ++j) o[i][j] += a * b[j];
            }
        }
    }

    const int b = bh >> 4;
    const int h = bh & 15;
#pragma unroll
    for (int i = 0; i < 4; ++i) {
        const int   row = qt * 128 + ty * 4 + i;
        const float inv = 1.0f / l[i];
        float* op = &g_att[((size_t)(b * Tn + row)) * Cn + h * 64 + tx * 8];
        *(float4*)&op[0] = make_float4(o[i][0] * inv, o[i][1] * inv,
                                       o[i][2] * inv, o[i][3] * inv);
        *(float4*)&op[4] = make_float4(o[i][4] * inv, o[i][5] * inv,
                                       o[i][6] * inv, o[i][7] * inv);
    }
}

// ---------------------------------------------------------------------------
extern "C" void kernel_launch(void* const* d_in, const int* in_sizes, int n_in,
                              void* d_out, int out_size)
{
    (void)in_sizes; (void)n_in; (void)out_size;
    const float* x  = (const float*)d_in[0];
    const float* Wq = (const float*)d_in[1];
    const float* Wk = (const float*)d_in[2];
    const float* Wv = (const float*)d_in[3];
    const float* Wo = (const float*)d_in[4];
    const float* bo = (const float*)d_in[5];
    float* out = (float*)d_out;

    cudaFuncSetAttribute(attn_kernel,     cudaFuncAttributeMaxDynamicSharedMemorySize, SMEM_ATTN);
    cudaFuncSetAttribute(qkv_mma_kernel,  cudaFuncAttributeMaxDynamicSharedMemorySize, SMEM_GEMM);
    cudaFuncSetAttribute(proj_mma_kernel, cudaFuncAttributeMaxDynamicSharedMemorySize, SMEM_GEMM);

    // conversions
    split_kernel<<<(Mtot * Cn / 4 + 255) / 256, 256>>>(x, Mtot * Cn / 4, 0);
    convw_kernel<<<dim3(3 * Hn, Cn / 64), 256>>>(Wq, Wk, Wv);
    split_kernel<<<(Cn * Cn / 4 + 255) / 256, 256>>>(Wo, Cn * Cn / 4, 2);

    // QKV projection (mma.sync tensor path)
    qkv_mma_kernel<<<dim3(Mtot / 128, 3 * Cn / 128), 256, SMEM_GEMM>>>();

    // attention (fp32 SIMT, register-tiled)
    attn_kernel<<<dim3(Tn / 128, Bn * Hn), 256, SMEM_ATTN>>>();

    // convert attention output, then output projection (mma.sync tensor path)
    split_kernel<<<(Mtot * Cn / 4 + 255) / 256, 256>>>(x, Mtot * Cn / 4, 1);
    proj_mma_kernel<<<dim3(Mtot / 128, Cn / 128), 256, SMEM_GEMM>>>(bo, out);
}

// round 14
// speedup vs baseline: 3.8230x; 2.1061x over previous
#include <cuda_runtime.h>
#include <cuda_bf16.h>
#include <cstdint>

#define Bn   4
#define Tn   2048
#define Cn   1024
#define Hn   16
#define HSn  64
#define Mtot (Bn * Tn)   // 8192

// ---------------------------------------------------------------------------
// Scratch (static device globals: allocation-free, graph-capturable)
// ---------------------------------------------------------------------------
__device__ __nv_bfloat16 g_xhi[Mtot * Cn];
__device__ __nv_bfloat16 g_xlo[Mtot * Cn];
__device__ __nv_bfloat16 g_ahi[Mtot * Cn];      // attention out (concat heads)
__device__ __nv_bfloat16 g_alo[Mtot * Cn];
__device__ __nv_bfloat16 g_wthi[3 * Cn * Cn];   // Wt[n][k]
__device__ __nv_bfloat16 g_wtlo[3 * Cn * Cn];
__device__ __nv_bfloat16 g_wohi[Cn * Cn];       // Wo[n][k]
__device__ __nv_bfloat16 g_wolo[Cn * Cn];

// bf16 hi/lo q,k ([B,H,T,HS]) and transposed v ([B,H,HS,T])
__device__ __nv_bfloat16 g_qhi[Bn * Hn * Tn * HSn];
__device__ __nv_bfloat16 g_qlo[Bn * Hn * Tn * HSn];
__device__ __nv_bfloat16 g_khi[Bn * Hn * Tn * HSn];
__device__ __nv_bfloat16 g_klo[Bn * Hn * Tn * HSn];
__device__ __nv_bfloat16 g_vthi[Bn * Hn * HSn * Tn];
__device__ __nv_bfloat16 g_vtlo[Bn * Hn * HSn * Tn];

// ---------------------------------------------------------------------------
// Helpers
// ---------------------------------------------------------------------------
static __device__ __forceinline__ uint32_t smem_u32(const void* p) {
    uint32_t a;
    asm("{ .reg .u64 t; cvta.to.shared.u64 t, %1; cvt.u32.u64 %0, t; }"
        : "=r"(a) : "l"(p));
    return a;
}
static __device__ __forceinline__ void ldsm4(uint32_t* r, uint32_t addr) {
    asm volatile("ldmatrix.sync.aligned.m8n8.x4.shared.b16 {%0,%1,%2,%3}, [%4];"
                 : "=r"(r[0]), "=r"(r[1]), "=r"(r[2]), "=r"(r[3]) : "r"(addr));
}
static __device__ __forceinline__ void mma16816(float* d, const uint32_t* a,
                                                const uint32_t* b) {
    asm volatile(
        "mma.sync.aligned.m16n8k16.row.col.f32.bf16.bf16.f32 "
        "{%0,%1,%2,%3}, {%4,%5,%6,%7}, {%8,%9}, {%0,%1,%2,%3};"
        : "+f"(d[0]), "+f"(d[1]), "+f"(d[2]), "+f"(d[3])
        : "r"(a[0]), "r"(a[1]), "r"(a[2]), "r"(a[3]), "r"(b[0]), "r"(b[1]));
}
static __device__ __forceinline__ unsigned pack2(__nv_bfloat16 a, __nv_bfloat16 b) {
    return (unsigned)__bfloat16_as_ushort(b) << 16 | (unsigned)__bfloat16_as_ushort(a);
}
static __device__ __forceinline__ void split1(float v, __nv_bfloat16& h, __nv_bfloat16& l) {
    h = __float2bfloat16(v);
    l = __float2bfloat16(v - __bfloat162float(h));
}

// ---------------------------------------------------------------------------
// Conversion kernels
// ---------------------------------------------------------------------------
__global__ __launch_bounds__(256) void split_kernel(const float* __restrict__ src,
                                                    int n4, int mode)
{
    int i = blockIdx.x * 256 + threadIdx.x;
    if (i >= n4) return;
    __nv_bfloat16* hi = (mode == 0) ? g_xhi : g_wohi;
    __nv_bfloat16* lo = (mode == 0) ? g_xlo : g_wolo;

    float4 v = ((const float4*)src)[i];
    __nv_bfloat16 h0, h1, h2, h3, l0, l1, l2, l3;
    split1(v.x, h0, l0); split1(v.y, h1, l1);
    split1(v.z, h2, l2); split1(v.w, h3, l3);

    uint2 uh; uh.x = pack2(h0, h1); uh.y = pack2(h2, h3);
    uint2 ul; ul.x = pack2(l0, l1); ul.y = pack2(l2, l3);
    *(uint2*)(hi + 4 * (size_t)i) = uh;
    *(uint2*)(lo + 4 * (size_t)i) = ul;
}

// Wq/Wk/Wv [h][c][d] -> Wt[n=(w*16+h)*64+d][k=c] bf16 hi/lo
__global__ __launch_bounds__(256) void convw_kernel(const float* __restrict__ Wq,
                                                    const float* __restrict__ Wk,
                                                    const float* __restrict__ Wv)
{
    __shared__ float s[64][65];
    const int wh = blockIdx.x;
    const int c0 = blockIdx.y * 64;
    const int w  = wh >> 4;
    const int h  = wh & 15;
    const float* W = ((w == 0) ? Wq : (w == 1) ? Wk : Wv) + (size_t)h * Cn * HSn;
    const int tid = threadIdx.x;

#pragma unroll
    for (int i = 0; i < 16; ++i) {
        int idx = tid + i * 256;
        int r = idx >> 6, d = idx & 63;
        s[r][d] = W[(size_t)(c0 + r) * 64 + d];
    }
    __syncthreads();
#pragma unroll
    for (int i = 0; i < 16; ++i) {
        int idx = tid + i * 256;
        int dd = idx >> 6, cc = idx & 63;
        __nv_bfloat16 hv, lv;
        split1(s[cc][dd], hv, lv);
        size_t o = (size_t)(wh * 64 + dd) * Cn + c0 + cc;
        g_wthi[o] = hv;
        g_wtlo[o] = lv;
    }
}

// ---------------------------------------------------------------------------
// mma.sync GEMM mainloop (identical to passing R12 version)
// ---------------------------------------------------------------------------
#define KC      32
#define NKC     (Cn / KC)
#define LDSW    40
#define TILE_B  (128 * LDSW * 2)
#define STAGE_B (4 * TILE_B)
#define SMEM_GEMM (2 * STAGE_B)

static __device__ __forceinline__ void issue_stage(
    uint32_t sb, int buf, int k0, int tid,
    const __nv_bfloat16* Ah, const __nv_bfloat16* Al,
    const __nv_bfloat16* Bh, const __nv_bfloat16* Bl)
{
    const __nv_bfloat16* srcs[4] = { Ah, Al, Bh, Bl };
#pragma unroll
    for (int q = 0; q < 4; ++q) {
#pragma unroll
        for (int l = 0; l < 2; ++l) {
            int t  = tid + l * 256;
            int r  = t >> 2;
            int c8 = (t & 3) * 8;
            uint32_t sa = sb + buf * STAGE_B + q * TILE_B + 2 * (r * LDSW + c8);
            const __nv_bfloat16* ga = srcs[q] + (size_t)r * Cn + k0 + c8;
            asm volatile("cp.async.cg.shared.global [%0], [%1], 16;"
                         :: "r"(sa), "l"(ga));
        }
    }
    asm volatile("cp.async.commit_group;" ::: "memory");
}

static __device__ __forceinline__ void gemm_mainloop(
    const __nv_bfloat16* Ah, const __nv_bfloat16* Al,
    const __nv_bfloat16* Bh, const __nv_bfloat16* Bl,
    char* smem, float acc[4][4][4])
{
    const int tid  = threadIdx.x;
    const int lane = tid & 31;
    const int warp = tid >> 5;
    const int wm   = (warp & 1) * 64;
    const int wn   = (warp >> 1) * 32;
    const uint32_t sb = smem_u32(smem);

    const int arow = lane & 15;
    const int acol = (lane >> 4) * 8;
    const int brow = (lane & 7) + 8 * (lane >> 4);
    const int bcol = 8 * ((lane >> 3) & 1);

#pragma unroll
    for (int mi = 0; mi < 4; ++mi)
#pragma unroll
        for (int ni = 0; ni < 4; ++ni)
#pragma unroll
            for (int e = 0; e < 4; ++e) acc[mi][ni][e] = 0.f;

    issue_stage(sb, 0, 0, tid, Ah, Al, Bh, Bl);

#pragma unroll 1
    for (int kc = 0; kc < NKC; ++kc) {
        const int cur = kc & 1;
        if (kc < NKC - 1) {
            issue_stage(sb, 1 - cur, (kc + 1) * KC, tid, Ah, Al, Bh, Bl);
            asm volatile("cp.async.wait_group 1;" ::: "memory");
        } else {
            asm volatile("cp.async.wait_group 0;" ::: "memory");
        }
        __syncthreads();

        const uint32_t abase = sb + cur * STAGE_B;
#pragma unroll
        for (int s = 0; s < 2; ++s) {
            const int k16 = s * 16;
            uint32_t ah[4][4], al[4][4];
#pragma unroll
            for (int mi = 0; mi < 4; ++mi) {
                uint32_t ra = abase + 2 * ((wm + mi * 16 + arow) * LDSW + k16 + acol);
                ldsm4(ah[mi], ra);
                ldsm4(al[mi], ra + TILE_B);
            }
            uint32_t bh[2][4], bl[2][4];
#pragma unroll
            for (int nb = 0; nb < 2; ++nb) {
                uint32_t rb = abase + 2 * TILE_B
                            + 2 * ((wn + nb * 16 + brow) * LDSW + k16 + bcol);
                ldsm4(bh[nb], rb);
                ldsm4(bl[nb], rb + TILE_B);
            }
#pragma unroll
            for (int mi = 0; mi < 4; ++mi)
#pragma unroll
                for (int ni = 0; ni < 4; ++ni) {
                    const uint32_t* bp  = &bh[ni >> 1][(ni & 1) * 2];
                    const uint32_t* blp = &bl[ni >> 1][(ni & 1) * 2];
                    mma16816(acc[mi][ni], ah[mi], bp);
                    mma16816(acc[mi][ni], al[mi], bp);
                    mma16816(acc[mi][ni], ah[mi], blp);
                }
        }
        __syncthreads();
    }
}

// ---------------------------------------------------------------------------
// QKV GEMM: epilogue emits bf16 hi/lo q (pre-scaled), k, and TRANSPOSED v.
// ---------------------------------------------------------------------------
__global__ __launch_bounds__(256) void qkv_mma_kernel()
{
    extern __shared__ char smem[];
    const int mbase = blockIdx.x * 128;
    const int nglob = blockIdx.y * 128;

    float acc[4][4][4];
    gemm_mainloop(g_xhi + (size_t)mbase * Cn, g_xlo + (size_t)mbase * Cn,
                  g_wthi + (size_t)nglob * Cn, g_wtlo + (size_t)nglob * Cn,
                  smem, acc);

    const int lane = threadIdx.x & 31;
    const int warp = threadIdx.x >> 5;
    const int wm = (warp & 1) * 64;
    const int wn = (warp >> 1) * 32;
    const int g  = lane >> 2;
    const int tg = lane & 3;

    const int w  = nglob >> 10;
    const int nn = nglob & 1023;
    const float sc = (w == 0) ? 0.125f : 1.0f;

#pragma unroll
    for (int mi = 0; mi < 4; ++mi) {
        const int m0 = mbase + wm + mi * 16 + g;
        const int b  = m0 >> 11;
        const int t0 = m0 & (Tn - 1);
#pragma unroll
        for (int ni = 0; ni < 4; ++ni) {
            const int n  = nn + wn + ni * 8 + 2 * tg;
            const int h  = n >> 6;
            const int d  = n & 63;
            const int bh = b * Hn + h;
            float v0 = acc[mi][ni][0] * sc, v1 = acc[mi][ni][1] * sc;
            float v2 = acc[mi][ni][2] * sc, v3 = acc[mi][ni][3] * sc;
            __nv_bfloat16 h0, h1, h2, h3, l0, l1, l2, l3;
            split1(v0, h0, l0); split1(v1, h1, l1);
            split1(v2, h2, l2); split1(v3, h3, l3);

            if (w == 2) {
                // vt[b,h][d][t]: (d,t0)=v0 (d+1,t0)=v1 (d,t0+8)=v2 (d+1,t0+8)=v3
                size_t base = ((size_t)bh * HSn + d) * Tn + t0;
                g_vthi[base]          = h0;  g_vtlo[base]          = l0;
                g_vthi[base + Tn]     = h1;  g_vtlo[base + Tn]     = l1;
                g_vthi[base + 8]      = h2;  g_vtlo[base + 8]      = l2;
                g_vthi[base + Tn + 8] = h3;  g_vtlo[base + Tn + 8] = l3;
            } else {
                __nv_bfloat16* dh = (w == 0) ? g_qhi : g_khi;
                __nv_bfloat16* dl = (w == 0) ? g_qlo : g_klo;
                size_t base = ((size_t)bh * Tn + t0) * HSn + d;
                *(uint32_t*)(dh + base)           = pack2(h0, h1);
                *(uint32_t*)(dl + base)           = pack2(l0, l1);
                *(uint32_t*)(dh + base + 8 * HSn) = pack2(h2, h3);
                *(uint32_t*)(dl + base + 8 * HSn) = pack2(l2, l3);
            }
        }
    }
}

// ---------------------------------------------------------------------------
// Output projection GEMM: out = att @ Wo^T + bo (R12, unchanged)
// ---------------------------------------------------------------------------
__global__ __launch_bounds__(256) void proj_mma_kernel(const float* __restrict__ bo,
                                                       float* __restrict__ out)
{
    extern __shared__ char smem[];
    const int mbase = blockIdx.x * 128;
    const int nbase = blockIdx.y * 128;

    float acc[4][4][4];
    gemm_mainloop(g_ahi + (size_t)mbase * Cn, g_alo + (size_t)mbase * Cn,
                  g_wohi + (size_t)nbase * Cn, g_wolo + (size_t)nbase * Cn,
                  smem, acc);

    const int lane = threadIdx.x & 31;
    const int warp = threadIdx.x >> 5;
    const int wm = (warp & 1) * 64;
    const int wn = (warp >> 1) * 32;
    const int g  = lane >> 2;
    const int tg = lane & 3;

#pragma unroll
    for (int mi = 0; mi < 4; ++mi) {
        const int m0 = mbase + wm + mi * 16 + g;
#pragma unroll
        for (int ni = 0; ni < 4; ++ni) {
            const int n = nbase + wn + ni * 8 + 2 * tg;
            const float bx = bo[n], by = bo[n + 1];
            float* p0 = out + (size_t)m0 * Cn + n;
            float* p1 = p0 + 8 * Cn;
            *(float2*)p0 = make_float2(acc[mi][ni][0] + bx, acc[mi][ni][1] + by);
            *(float2*)p1 = make_float2(acc[mi][ni][2] + bx, acc[mi][ni][3] + by);
        }
    }
}

// ---------------------------------------------------------------------------
// Tensor-core causal flash attention (mma.sync, hi/lo split both GEMMs).
// 256 threads, 8 warps; warp w owns q-rows [qt*128 + w*16, +16).
// Smem (bf16, stride 72): phase 1 Qstage hi[128][72] lo[128][72];
// phase 2 per key-tile: Khi, Klo [64][72] (rows=key, cols=d),
//                       Vthi, Vtlo [64][72] (rows=d, cols=key).
// ---------------------------------------------------------------------------
#define ATT_SMEM 36864
#define QH_S 0
#define QL_S 9216
#define KH_S 0
#define KL_S 4608
#define VH_S 9216
#define VL_S 13824

__global__ __launch_bounds__(256) void attn_mma_kernel()
{
    extern __shared__ char smraw[];
    __nv_bfloat16* sm2 = (__nv_bfloat16*)smraw;
    const int tid  = threadIdx.x;
    const int lane = tid & 31;
    const int w    = tid >> 5;
    const int qt   = blockIdx.x;   // 0..15
    const int bh   = blockIdx.y;   // 0..63
    const uint32_t sb = smem_u32(sm2);

    const int g  = lane >> 2;
    const int t4 = lane & 3;
    const int krow_l = (lane & 7) + 8 * (lane >> 4);     // proven B row map
    const int kcol_l = ((lane >> 3) & 1) * 8;            // proven B col map

    // ---- stage Q (hi/lo) and load A-fragments into registers ----
    {
        const __nv_bfloat16* Qh = g_qhi + ((size_t)bh * Tn + qt * 128) * HSn;
        const __nv_bfloat16* Ql = g_qlo + ((size_t)bh * Tn + qt * 128) * HSn;
#pragma unroll
        for (int i = 0; i < 4; ++i) {
            int c = tid + i * 256;          // 1024 8-elem chunks
            int r = c >> 3, c8 = (c & 7) * 8;
            *(uint4*)(sm2 + QH_S + r * 72 + c8) = *(const uint4*)(Qh + (size_t)r * HSn + c8);
            *(uint4*)(sm2 + QL_S + r * 72 + c8) = *(const uint4*)(Ql + (size_t)r * HSn + c8);
        }
    }
    __syncthreads();

    uint32_t qh[4][4], ql[4][4];
    {
        const int qrow_l = w * 16 + (lane & 15);
        const int qcol_l = 8 * (lane >> 4);
#pragma unroll
        for (int kk = 0; kk < 4; ++kk) {
            uint32_t a = sb + 2 * (QH_S + qrow_l * 72 + kk * 16 + qcol_l);
            ldsm4(qh[kk], a);
            ldsm4(ql[kk], a + 2 * (QL_S - QH_S));
        }
    }

    float m_[2] = { -1e30f, -1e30f };
    float l_[2] = { 0.f, 0.f };
    float o[8][4];
#pragma unroll
    for (int j = 0; j < 8; ++j)
#pragma unroll
        for (int e = 0; e < 4; ++e) o[j][e] = 0.f;

    const __nv_bfloat16* Kh  = g_khi  + (size_t)bh * Tn * HSn;
    const __nv_bfloat16* Kl  = g_klo  + (size_t)bh * Tn * HSn;
    const __nv_bfloat16* Vth = g_vthi + (size_t)bh * HSn * Tn;
    const __nv_bfloat16* Vtl = g_vtlo + (size_t)bh * HSn * Tn;

    const int warp_qmax = qt * 128 + w * 16 + 15;
    const int nkt = qt * 2 + 2;

#pragma unroll 1
    for (int kt = 0; kt < nkt; ++kt) {
        __syncthreads();
        // fill K (rows=key, cols=d) and Vt (rows=d, cols=key)
#pragma unroll
        for (int i = 0; i < 2; ++i) {
            int c = tid + i * 256;          // 512 chunks per array
            int r = c >> 3, c8 = (c & 7) * 8;
            *(uint4*)(sm2 + KH_S + r * 72 + c8) = *(const uint4*)(Kh  + (size_t)(kt * 64 + r) * HSn + c8);
            *(uint4*)(sm2 + KL_S + r * 72 + c8) = *(const uint4*)(Kl  + (size_t)(kt * 64 + r) * HSn + c8);
            *(uint4*)(sm2 + VH_S + r * 72 + c8) = *(const uint4*)(Vth + (size_t)r * Tn + kt * 64 + c8);
            *(uint4*)(sm2 + VL_S + r * 72 + c8) = *(const uint4*)(Vtl + (size_t)r * Tn + kt * 64 + c8);
        }
        __syncthreads();

        if (kt * 64 > warp_qmax) continue;   // fully-masked tile for this warp

        // ---- scores: s[8 n-tiles][4], QK^T with 3-way split ----
        float s[8][4];
#pragma unroll
        for (int j = 0; j < 8; ++j)
#pragma unroll
            for (int e = 0; e < 4; ++e) s[j][e] = 0.f;

#pragma unroll
        for (int kk = 0; kk < 4; ++kk) {
#pragma unroll
            for (int j2 = 0; j2 < 4; ++j2) {
                uint32_t kbh[4], kbl[4];
                uint32_t addr = sb + 2 * (KH_S + (j2 * 16 + krow_l) * 72 + kk * 16 + kcol_l);
                ldsm4(kbh, addr);
                ldsm4(kbl, addr + 2 * (KL_S - KH_S));
                mma16816(s[2 * j2],     qh[kk], kbh);
                mma16816(s[2 * j2],     ql[kk], kbh);
                mma16816(s[2 * j2],     qh[kk], kbl);
                mma16816(s[2 * j2 + 1], qh[kk], kbh + 2);
                mma16816(s[2 * j2 + 1], ql[kk], kbh + 2);
                mma16816(s[2 * j2 + 1], qh[kk], kbl + 2);
            }
        }

        // ---- causal mask (diagonal tiles only; warp-uniform branch) ----
        if (kt >= 2 * qt) {
            const int qrow0 = qt * 128 + w * 16 + g;
#pragma unroll
            for (int j = 0; j < 8; ++j)
#pragma unroll
                for (int e = 0; e < 4; ++e) {
                    int key = kt * 64 + j * 8 + 2 * t4 + (e & 1);
                    int row = qrow0 + (e >> 1) * 8;
                    if (key > row) s[j][e] = -1e30f;
                }
        }

        // ---- online softmax per row-half ----
#pragma unroll
        for (int rh = 0; rh < 2; ++rh) {
            float mx = -1e30f;
#pragma unroll
            for (int j = 0; j < 8; ++j) {
                mx = fmaxf(mx, s[j][rh * 2]);
                mx = fmaxf(mx, s[j][rh * 2 + 1]);
            }
            mx = fmaxf(mx, __shfl_xor_sync(0xffffffffu, mx, 1));
            mx = fmaxf(mx, __shfl_xor_sync(0xffffffffu, mx, 2));
            const float mn = fmaxf(m_[rh], mx);
            const float scale = __expf(m_[rh] - mn);
            float ps = 0.f;
#pragma unroll
            for (int j = 0; j < 8; ++j) {
                s[j][rh * 2]     = __expf(s[j][rh * 2] - mn);
                s[j][rh * 2 + 1] = __expf(s[j][rh * 2 + 1] - mn);
                ps += s[j][rh * 2] + s[j][rh * 2 + 1];
            }
            ps += __shfl_xor_sync(0xffffffffu, ps, 1);
            ps += __shfl_xor_sync(0xffffffffu, ps, 2);
            l_[rh] = l_[rh] * scale + ps;
            m_[rh] = mn;
#pragma unroll
            for (int j = 0; j < 8; ++j) {
                o[j][rh * 2]     *= scale;
                o[j][rh * 2 + 1] *= scale;
            }
        }

        // ---- PV: o[8 d-tiles][4] += P * V, 3-way split ----
#pragma unroll
        for (int c = 0; c < 4; ++c) {
            // build P A-fragments in registers from score tiles 2c, 2c+1
            uint32_t pah[4], pal[4];
#pragma unroll
            for (int half = 0; half < 2; ++half) {
                const float* pv = s[2 * c + half];
                __nv_bfloat16 h0, h1, h2, h3, l0, l1, l2, l3;
                split1(pv[0], h0, l0); split1(pv[1], h1, l1);
                split1(pv[2], h2, l2); split1(pv[3], h3, l3);
                pah[half * 2]     = pack2(h0, h1);
                pah[half * 2 + 1] = pack2(h2, h3);
                pal[half * 2]     = pack2(l0, l1);
                pal[half * 2 + 1] = pack2(l2, l3);
            }
#pragma unroll
            for (int j2 = 0; j2 < 4; ++j2) {
                uint32_t vbh[4], vbl[4];
                uint32_t addr = sb + 2 * (VH_S + (j2 * 16 + krow_l) * 72 + c * 16 + kcol_l);
                ldsm4(vbh, addr);
                ldsm4(vbl, addr + 2 * (VL_S - VH_S));
                mma16816(o[2 * j2],     pah, vbh);
                mma16816(o[2 * j2],     pal, vbh);
                mma16816(o[2 * j2],     pah, vbl);
                mma16816(o[2 * j2 + 1], pah, vbh + 2);
                mma16816(o[2 * j2 + 1], pal, vbh + 2);
                mma16816(o[2 * j2 + 1], pah, vbl + 2);
            }
        }
    }

    // ---- epilogue: write bf16 hi/lo att (concat-head [B,T,C]) ----
    const int b = bh >> 4;
    const int h = bh & 15;
#pragma unroll
    for (int rh = 0; rh < 2; ++rh) {
        const float inv = 1.0f / l_[rh];
        const int   row = qt * 128 + w * 16 + g + rh * 8;
#pragma unroll
        for (int j = 0; j < 8; ++j) {
            const int d = j * 8 + 2 * t4;
            float v0 = o[j][rh * 2] * inv;
            float v1 = o[j][rh * 2 + 1] * inv;
            __nv_bfloat16 h0, h1, l0, l1;
            split1(v0, h0, l0); split1(v1, h1, l1);
            size_t off = ((size_t)(b * Tn + row)) * Cn + h * 64 + d;
            *(uint32_t*)(g_ahi + off) = pack2(h0, h1);
            *(uint32_t*)(g_alo + off) = pack2(l0, l1);
        }
    }
}

// ---------------------------------------------------------------------------
extern "C" void kernel_launch(void* const* d_in, const int* in_sizes, int n_in,
                              void* d_out, int out_size)
{
    (void)in_sizes; (void)n_in; (void)out_size;
    const float* x  = (const float*)d_in[0];
    const float* Wq = (const float*)d_in[1];
    const float* Wk = (const float*)d_in[2];
    const float* Wv = (const float*)d_in[3];
    const float* Wo = (const float*)d_in[4];
    const float* bo = (const float*)d_in[5];
    float* out = (float*)d_out;

    cudaFuncSetAttribute(qkv_mma_kernel,  cudaFuncAttributeMaxDynamicSharedMemorySize, SMEM_GEMM);
    cudaFuncSetAttribute(proj_mma_kernel, cudaFuncAttributeMaxDynamicSharedMemorySize, SMEM_GEMM);
    cudaFuncSetAttribute(attn_mma_kernel, cudaFuncAttributeMaxDynamicSharedMemorySize, ATT_SMEM);

    // conversions (x and Wo)
    split_kernel<<<(Mtot * Cn / 4 + 255) / 256, 256>>>(x, Mtot * Cn / 4, 0);
    convw_kernel<<<dim3(3 * Hn, Cn / 64), 256>>>(Wq, Wk, Wv);
    split_kernel<<<(Cn * Cn / 4 + 255) / 256, 256>>>(Wo, Cn * Cn / 4, 2);

    // QKV projection -> bf16 hi/lo q,k,vt
    qkv_mma_kernel<<<dim3(Mtot / 128, 3 * Cn / 128), 256, SMEM_GEMM>>>();

    // attention (tensor cores) -> g_ahi/g_alo
    attn_mma_kernel<<<dim3(Tn / 128, Bn * Hn), 256, ATT_SMEM>>>();

    // output projection
    proj_mma_kernel<<<dim3(Mtot / 128, Cn / 128), 256, SMEM_GEMM>>>(bo, out);
}

// round 16
// speedup vs baseline: 3.9880x; 1.0432x over previous
#include <cuda_runtime.h>
#include <cuda_bf16.h>
#include <cstdint>

#define Bn   4
#define Tn   2048
#define Cn   1024
#define Hn   16
#define HSn  64
#define Mtot (Bn * Tn)   // 8192

// ---------------------------------------------------------------------------
// Scratch (static device globals: allocation-free, graph-capturable)
// ---------------------------------------------------------------------------
__device__ __nv_bfloat16 g_xhi[Mtot * Cn];
__device__ __nv_bfloat16 g_xlo[Mtot * Cn];
__device__ __nv_bfloat16 g_ahi[Mtot * Cn];      // attention out (concat heads)
__device__ __nv_bfloat16 g_alo[Mtot * Cn];
__device__ __nv_bfloat16 g_wthi[3 * Cn * Cn];   // Wt[n][k]
__device__ __nv_bfloat16 g_wtlo[3 * Cn * Cn];
__device__ __nv_bfloat16 g_wohi[Cn * Cn];       // Wo[n][k]
__device__ __nv_bfloat16 g_wolo[Cn * Cn];

// bf16 hi/lo q,k ([B,H,T,HS]) and transposed v ([B,H,HS,T])
__device__ __nv_bfloat16 g_qhi[Bn * Hn * Tn * HSn];
__device__ __nv_bfloat16 g_qlo[Bn * Hn * Tn * HSn];
__device__ __nv_bfloat16 g_khi[Bn * Hn * Tn * HSn];
__device__ __nv_bfloat16 g_klo[Bn * Hn * Tn * HSn];
__device__ __nv_bfloat16 g_vthi[Bn * Hn * HSn * Tn];
__device__ __nv_bfloat16 g_vtlo[Bn * Hn * HSn * Tn];

// ---------------------------------------------------------------------------
// Helpers
// ---------------------------------------------------------------------------
static __device__ __forceinline__ uint32_t smem_u32(const void* p) {
    uint32_t a;
    asm("{ .reg .u64 t; cvta.to.shared.u64 t, %1; cvt.u32.u64 %0, t; }"
        : "=r"(a) : "l"(p));
    return a;
}
static __device__ __forceinline__ void ldsm4(uint32_t* r, uint32_t addr) {
    asm volatile("ldmatrix.sync.aligned.m8n8.x4.shared.b16 {%0,%1,%2,%3}, [%4];"
                 : "=r"(r[0]), "=r"(r[1]), "=r"(r[2]), "=r"(r[3]) : "r"(addr));
}
static __device__ __forceinline__ void mma16816(float* d, const uint32_t* a,
                                                const uint32_t* b) {
    asm volatile(
        "mma.sync.aligned.m16n8k16.row.col.f32.bf16.bf16.f32 "
        "{%0,%1,%2,%3}, {%4,%5,%6,%7}, {%8,%9}, {%0,%1,%2,%3};"
        : "+f"(d[0]), "+f"(d[1]), "+f"(d[2]), "+f"(d[3])
        : "r"(a[0]), "r"(a[1]), "r"(a[2]), "r"(a[3]), "r"(b[0]), "r"(b[1]));
}
static __device__ __forceinline__ void cpa16(uint32_t dst, const void* src) {
    asm volatile("cp.async.cg.shared.global [%0], [%1], 16;" :: "r"(dst), "l"(src));
}
static __device__ __forceinline__ unsigned pack2(__nv_bfloat16 a, __nv_bfloat16 b) {
    return (unsigned)__bfloat16_as_ushort(b) << 16 | (unsigned)__bfloat16_as_ushort(a);
}
static __device__ __forceinline__ void split1(float v, __nv_bfloat16& h, __nv_bfloat16& l) {
    h = __float2bfloat16(v);
    l = __float2bfloat16(v - __bfloat162float(h));
}

// ---------------------------------------------------------------------------
// Conversion kernels
// ---------------------------------------------------------------------------
__global__ __launch_bounds__(256) void split_kernel(const float* __restrict__ src,
                                                    int n4, int mode)
{
    int i = blockIdx.x * 256 + threadIdx.x;
    if (i >= n4) return;
    __nv_bfloat16* hi = (mode == 0) ? g_xhi : g_wohi;
    __nv_bfloat16* lo = (mode == 0) ? g_xlo : g_wolo;

    float4 v = ((const float4*)src)[i];
    __nv_bfloat16 h0, h1, h2, h3, l0, l1, l2, l3;
    split1(v.x, h0, l0); split1(v.y, h1, l1);
    split1(v.z, h2, l2); split1(v.w, h3, l3);

    uint2 uh; uh.x = pack2(h0, h1); uh.y = pack2(h2, h3);
    uint2 ul; ul.x = pack2(l0, l1); ul.y = pack2(l2, l3);
    *(uint2*)(hi + 4 * (size_t)i) = uh;
    *(uint2*)(lo + 4 * (size_t)i) = ul;
}

// Wq/Wk/Wv [h][c][d] -> Wt[n=(w*16+h)*64+d][k=c] bf16 hi/lo
__global__ __launch_bounds__(256) void convw_kernel(const float* __restrict__ Wq,
                                                    const float* __restrict__ Wk,
                                                    const float* __restrict__ Wv)
{
    __shared__ float s[64][65];
    const int wh = blockIdx.x;
    const int c0 = blockIdx.y * 64;
    const int w  = wh >> 4;
    const int h  = wh & 15;
    const float* W = ((w == 0) ? Wq : (w == 1) ? Wk : Wv) + (size_t)h * Cn * HSn;
    const int tid = threadIdx.x;

#pragma unroll
    for (int i = 0; i < 16; ++i) {
        int idx = tid + i * 256;
        int r = idx >> 6, d = idx & 63;
        s[r][d] = W[(size_t)(c0 + r) * 64 + d];
    }
    __syncthreads();
#pragma unroll
    for (int i = 0; i < 16; ++i) {
        int idx = tid + i * 256;
        int dd = idx >> 6, cc = idx & 63;
        __nv_bfloat16 hv, lv;
        split1(s[cc][dd], hv, lv);
        size_t o = (size_t)(wh * 64 + dd) * Cn + c0 + cc;
        g_wthi[o] = hv;
        g_wtlo[o] = lv;
    }
}

// ---------------------------------------------------------------------------
// mma.sync GEMM mainloop (R12 structure; MMA nest reordered split-major so
// each accumulator is reused at distance 16 instead of back-to-back RAW)
// ---------------------------------------------------------------------------
#define KC      32
#define NKC     (Cn / KC)
#define LDSW    40
#define TILE_B  (128 * LDSW * 2)
#define STAGE_B (4 * TILE_B)
#define SMEM_GEMM (2 * STAGE_B)

static __device__ __forceinline__ void issue_stage(
    uint32_t sb, int buf, int k0, int tid,
    const __nv_bfloat16* Ah, const __nv_bfloat16* Al,
    const __nv_bfloat16* Bh, const __nv_bfloat16* Bl)
{
    const __nv_bfloat16* srcs[4] = { Ah, Al, Bh, Bl };
#pragma unroll
    for (int q = 0; q < 4; ++q) {
#pragma unroll
        for (int l = 0; l < 2; ++l) {
            int t  = tid + l * 256;
            int r  = t >> 2;
            int c8 = (t & 3) * 8;
            uint32_t sa = sb + buf * STAGE_B + q * TILE_B + 2 * (r * LDSW + c8);
            cpa16(sa, srcs[q] + (size_t)r * Cn + k0 + c8);
        }
    }
    asm volatile("cp.async.commit_group;" ::: "memory");
}

static __device__ __forceinline__ void gemm_mainloop(
    const __nv_bfloat16* Ah, const __nv_bfloat16* Al,
    const __nv_bfloat16* Bh, const __nv_bfloat16* Bl,
    char* smem, float acc[4][4][4])
{
    const int tid  = threadIdx.x;
    const int lane = tid & 31;
    const int warp = tid >> 5;
    const int wm   = (warp & 1) * 64;
    const int wn   = (warp >> 1) * 32;
    const uint32_t sb = smem_u32(smem);

    const int arow = lane & 15;
    const int acol = (lane >> 4) * 8;
    const int brow = (lane & 7) + 8 * (lane >> 4);
    const int bcol = 8 * ((lane >> 3) & 1);

#pragma unroll
    for (int mi = 0; mi < 4; ++mi)
#pragma unroll
        for (int ni = 0; ni < 4; ++ni)
#pragma unroll
            for (int e = 0; e < 4; ++e) acc[mi][ni][e] = 0.f;

    issue_stage(sb, 0, 0, tid, Ah, Al, Bh, Bl);

#pragma unroll 1
    for (int kc = 0; kc < NKC; ++kc) {
        const int cur = kc & 1;
        if (kc < NKC - 1) {
            issue_stage(sb, 1 - cur, (kc + 1) * KC, tid, Ah, Al, Bh, Bl);
            asm volatile("cp.async.wait_group 1;" ::: "memory");
        } else {
            asm volatile("cp.async.wait_group 0;" ::: "memory");
        }
        __syncthreads();

        const uint32_t abase = sb + cur * STAGE_B;
#pragma unroll
        for (int s = 0; s < 2; ++s) {
            const int k16 = s * 16;
            uint32_t ah[4][4], al[4][4];
#pragma unroll
            for (int mi = 0; mi < 4; ++mi) {
                uint32_t ra = abase + 2 * ((wm + mi * 16 + arow) * LDSW + k16 + acol);
                ldsm4(ah[mi], ra);
                ldsm4(al[mi], ra + TILE_B);
            }
            uint32_t bh[2][4], bl[2][4];
#pragma unroll
            for (int nb = 0; nb < 2; ++nb) {
                uint32_t rb = abase + 2 * TILE_B
                            + 2 * ((wn + nb * 16 + brow) * LDSW + k16 + bcol);
                ldsm4(bh[nb], rb);
                ldsm4(bl[nb], rb + TILE_B);
            }
            // split-major: 16 independent MMAs per pass; per-acc order is
            // still hh -> lh -> hl (bitwise-identical summation)
#pragma unroll
            for (int mi = 0; mi < 4; ++mi)
#pragma unroll
                for (int ni = 0; ni < 4; ++ni)
                    mma16816(acc[mi][ni], ah[mi], &bh[ni >> 1][(ni & 1) * 2]);
#pragma unroll
            for (int mi = 0; mi < 4; ++mi)
#pragma unroll
                for (int ni = 0; ni < 4; ++ni)
                    mma16816(acc[mi][ni], al[mi], &bh[ni >> 1][(ni & 1) * 2]);
#pragma unroll
            for (int mi = 0; mi < 4; ++mi)
#pragma unroll
                for (int ni = 0; ni < 4; ++ni)
                    mma16816(acc[mi][ni], ah[mi], &bl[ni >> 1][(ni & 1) * 2]);
        }
        __syncthreads();
    }
}

// ---------------------------------------------------------------------------
// QKV GEMM: epilogue emits bf16 hi/lo q (pre-scaled), k, and TRANSPOSED v.
// ---------------------------------------------------------------------------
__global__ __launch_bounds__(256) void qkv_mma_kernel()
{
    extern __shared__ char smem[];
    const int mbase = blockIdx.x * 128;
    const int nglob = blockIdx.y * 128;

    float acc[4][4][4];
    gemm_mainloop(g_xhi + (size_t)mbase * Cn, g_xlo + (size_t)mbase * Cn,
                  g_wthi + (size_t)nglob * Cn, g_wtlo + (size_t)nglob * Cn,
                  smem, acc);

    const int lane = threadIdx.x & 31;
    const int warp = threadIdx.x >> 5;
    const int wm = (warp & 1) * 64;
    const int wn = (warp >> 1) * 32;
    const int g  = lane >> 2;
    const int tg = lane & 3;

    const int w  = nglob >> 10;
    const int nn = nglob & 1023;
    const float sc = (w == 0) ? 0.125f : 1.0f;

#pragma unroll
    for (int mi = 0; mi < 4; ++mi) {
        const int m0 = mbase + wm + mi * 16 + g;
        const int b  = m0 >> 11;
        const int t0 = m0 & (Tn - 1);
#pragma unroll
        for (int ni = 0; ni < 4; ++ni) {
            const int n  = nn + wn + ni * 8 + 2 * tg;
            const int h  = n >> 6;
            const int d  = n & 63;
            const int bh = b * Hn + h;
            float v0 = acc[mi][ni][0] * sc, v1 = acc[mi][ni][1] * sc;
            float v2 = acc[mi][ni][2] * sc, v3 = acc[mi][ni][3] * sc;
            __nv_bfloat16 h0, h1, h2, h3, l0, l1, l2, l3;
            split1(v0, h0, l0); split1(v1, h1, l1);
            split1(v2, h2, l2); split1(v3, h3, l3);

            if (w == 2) {
                size_t base = ((size_t)bh * HSn + d) * Tn + t0;
                g_vthi[base]          = h0;  g_vtlo[base]          = l0;
                g_vthi[base + Tn]     = h1;  g_vtlo[base + Tn]     = l1;
                g_vthi[base + 8]      = h2;  g_vtlo[base + 8]      = l2;
                g_vthi[base + Tn + 8] = h3;  g_vtlo[base + Tn + 8] = l3;
            } else {
                __nv_bfloat16* dh = (w == 0) ? g_qhi : g_khi;
                __nv_bfloat16* dl = (w == 0) ? g_qlo : g_klo;
                size_t base = ((size_t)bh * Tn + t0) * HSn + d;
                *(uint32_t*)(dh + base)           = pack2(h0, h1);
                *(uint32_t*)(dl + base)           = pack2(l0, l1);
                *(uint32_t*)(dh + base + 8 * HSn) = pack2(h2, h3);
                *(uint32_t*)(dl + base + 8 * HSn) = pack2(l2, l3);
            }
        }
    }
}

// ---------------------------------------------------------------------------
// Output projection GEMM: out = att @ Wo^T + bo
// ---------------------------------------------------------------------------
__global__ __launch_bounds__(256) void proj_mma_kernel(const float* __restrict__ bo,
                                                       float* __restrict__ out)
{
    extern __shared__ char smem[];
    const int mbase = blockIdx.x * 128;
    const int nbase = blockIdx.y * 128;

    float acc[4][4][4];
    gemm_mainloop(g_ahi + (size_t)mbase * Cn, g_alo + (size_t)mbase * Cn,
                  g_wohi + (size_t)nbase * Cn, g_wolo + (size_t)nbase * Cn,
                  smem, acc);

    const int lane = threadIdx.x & 31;
    const int warp = threadIdx.x >> 5;
    const int wm = (warp & 1) * 64;
    const int wn = (warp >> 1) * 32;
    const int g  = lane >> 2;
    const int tg = lane & 3;

#pragma unroll
    for (int mi = 0; mi < 4; ++mi) {
        const int m0 = mbase + wm + mi * 16 + g;
#pragma unroll
        for (int ni = 0; ni < 4; ++ni) {
            const int n = nbase + wn + ni * 8 + 2 * tg;
            const float bx = bo[n], by = bo[n + 1];
            float* p0 = out + (size_t)m0 * Cn + n;
            float* p1 = p0 + 8 * Cn;
            *(float2*)p0 = make_float2(acc[mi][ni][0] + bx, acc[mi][ni][1] + by);
            *(float2*)p1 = make_float2(acc[mi][ni][2] + bx, acc[mi][ni][3] + by);
        }
    }
}

// ---------------------------------------------------------------------------
// Tensor-core causal flash attention (mma.sync, hi/lo split both GEMMs).
// 256 threads, 8 warps; warp w owns q-rows [qt*128 + w*16, +16).
// Smem: 2 x 18432-elem K/V buffers (cp.async double-buffered);
// buffer layout (elems): KH 0, KL 4608, VH 9216, VL 13824 (stride 72).
// Q is staged in buffer 0 before the mainloop (frags then live in regs).
// ---------------------------------------------------------------------------
#define BUF_E  18432
#define KH_E   0
#define KL_E   4608
#define VH_E   9216
#define VL_E   13824
#define ATT_SMEM (2 * BUF_E * 2)   // 73728 B

static __device__ __forceinline__ void attn_issue_tile(
    uint32_t sb, int buf, int kt, int tid,
    const __nv_bfloat16* Kh, const __nv_bfloat16* Kl,
    const __nv_bfloat16* Vth, const __nv_bfloat16* Vtl)
{
    const int base = buf * BUF_E;
#pragma unroll
    for (int i = 0; i < 2; ++i) {
        int c  = tid + i * 256;         // 512 chunks per array
        int r  = c >> 3;
        int c8 = (c & 7) * 8;
        cpa16(sb + 2 * (base + KH_E + r * 72 + c8), Kh  + (size_t)(kt * 64 + r) * HSn + c8);
        cpa16(sb + 2 * (base + KL_E + r * 72 + c8), Kl  + (size_t)(kt * 64 + r) * HSn + c8);
        cpa16(sb + 2 * (base + VH_E + r * 72 + c8), Vth + (size_t)r * Tn + kt * 64 + c8);
        cpa16(sb + 2 * (base + VL_E + r * 72 + c8), Vtl + (size_t)r * Tn + kt * 64 + c8);
    }
    asm volatile("cp.async.commit_group;" ::: "memory");
}

__global__ __launch_bounds__(256) void attn_mma_kernel()
{
    extern __shared__ char smraw[];
    __nv_bfloat16* sm2 = (__nv_bfloat16*)smraw;
    const int tid  = threadIdx.x;
    const int lane = tid & 31;
    const int w    = tid >> 5;
    const int qt   = blockIdx.x;   // 0..15
    const int bh   = blockIdx.y;   // 0..63
    const uint32_t sb = smem_u32(sm2);

    const int g  = lane >> 2;
    const int t4 = lane & 3;
    const int krow_l = (lane & 7) + 8 * (lane >> 4);
    const int kcol_l = ((lane >> 3) & 1) * 8;

    // ---- stage Q (hi/lo) into buffer 0, load A-fragments into registers ----
    {
        const __nv_bfloat16* Qh = g_qhi + ((size_t)bh * Tn + qt * 128) * HSn;
        const __nv_bfloat16* Ql = g_qlo + ((size_t)bh * Tn + qt * 128) * HSn;
#pragma unroll
        for (int i = 0; i < 4; ++i) {
            int c = tid + i * 256;
            int r = c >> 3, c8 = (c & 7) * 8;
            *(uint4*)(sm2 + r * 72 + c8)        = *(const uint4*)(Qh + (size_t)r * HSn + c8);
            *(uint4*)(sm2 + 9216 + r * 72 + c8) = *(const uint4*)(Ql + (size_t)r * HSn + c8);
        }
    }
    __syncthreads();

    uint32_t qh[4][4], ql[4][4];
    {
        const int qrow_l = w * 16 + (lane & 15);
        const int qcol_l = 8 * (lane >> 4);
#pragma unroll
        for (int kk = 0; kk < 4; ++kk) {
            uint32_t a = sb + 2 * (qrow_l * 72 + kk * 16 + qcol_l);
            ldsm4(qh[kk], a);
            ldsm4(ql[kk], a + 2 * 9216);
        }
    }
    __syncthreads();   // all warps done reading Q before buf0 is overwritten

    float m_[2] = { -1e30f, -1e30f };
    float l_[2] = { 0.f, 0.f };
    float o[8][4];
#pragma unroll
    for (int j = 0; j < 8; ++j)
#pragma unroll
        for (int e = 0; e < 4; ++e) o[j][e] = 0.f;

    const __nv_bfloat16* Kh  = g_khi  + (size_t)bh * Tn * HSn;
    const __nv_bfloat16* Kl  = g_klo  + (size_t)bh * Tn * HSn;
    const __nv_bfloat16* Vth = g_vthi + (size_t)bh * HSn * Tn;
    const __nv_bfloat16* Vtl = g_vtlo + (size_t)bh * HSn * Tn;

    const int warp_qmax = qt * 128 + w * 16 + 15;
    const int nkt = qt * 2 + 2;

    attn_issue_tile(sb, 0, 0, tid, Kh, Kl, Vth, Vtl);

#pragma unroll 1
    for (int kt = 0; kt < nkt; ++kt) {
        if (kt + 1 < nkt) {
            attn_issue_tile(sb, (kt + 1) & 1, kt + 1, tid, Kh, Kl, Vth, Vtl);
            asm volatile("cp.async.wait_group 1;" ::: "memory");
        } else {
            asm volatile("cp.async.wait_group 0;" ::: "memory");
        }
        __syncthreads();

        if (kt * 64 <= warp_qmax) {
            const int be = (kt & 1) * BUF_E;

            // ---- scores: QK^T, 3-way split, n-interleaved MMA order ----
            float s[8][4];
#pragma unroll
            for (int j = 0; j < 8; ++j)
#pragma unroll
                for (int e = 0; e < 4; ++e) s[j][e] = 0.f;

#pragma unroll
            for (int kk = 0; kk < 4; ++kk) {
#pragma unroll
                for (int j2 = 0; j2 < 4; ++j2) {
                    uint32_t kbh[4], kbl[4];
                    uint32_t addr = sb + 2 * (be + KH_E + (j2 * 16 + krow_l) * 72 + kk * 16 + kcol_l);
                    ldsm4(kbh, addr);
                    ldsm4(kbl, addr + 2 * (KL_E - KH_E));
                    mma16816(s[2 * j2],     qh[kk], kbh);
                    mma16816(s[2 * j2 + 1], qh[kk], kbh + 2);
                    mma16816(s[2 * j2],     ql[kk], kbh);
                    mma16816(s[2 * j2 + 1], ql[kk], kbh + 2);
                    mma16816(s[2 * j2],     qh[kk], kbl);
                    mma16816(s[2 * j2 + 1], qh[kk], kbl + 2);
                }
            }

            // ---- causal mask (diagonal tiles only) ----
            if (kt >= 2 * qt) {
                const int qrow0 = qt * 128 + w * 16 + g;
#pragma unroll
                for (int j = 0; j < 8; ++j)
#pragma unroll
                    for (int e = 0; e < 4; ++e) {
                        int key = kt * 64 + j * 8 + 2 * t4 + (e & 1);
                        int row = qrow0 + (e >> 1) * 8;
                        if (key > row) s[j][e] = -1e30f;
                    }
            }

            // ---- online softmax per row-half ----
#pragma unroll
            for (int rh = 0; rh < 2; ++rh) {
                float mx = -1e30f;
#pragma unroll
                for (int j = 0; j < 8; ++j) {
                    mx = fmaxf(mx, s[j][rh * 2]);
                    mx = fmaxf(mx, s[j][rh * 2 + 1]);
                }
                mx = fmaxf(mx, __shfl_xor_sync(0xffffffffu, mx, 1));
                mx = fmaxf(mx, __shfl_xor_sync(0xffffffffu, mx, 2));
                const float mn = fmaxf(m_[rh], mx);
                const float scale = __expf(m_[rh] - mn);
                float ps = 0.f;
#pragma unroll
                for (int j = 0; j < 8; ++j) {
                    s[j][rh * 2]     = __expf(s[j][rh * 2] - mn);
                    s[j][rh * 2 + 1] = __expf(s[j][rh * 2 + 1] - mn);
                    ps += s[j][rh * 2] + s[j][rh * 2 + 1];
                }
                ps += __shfl_xor_sync(0xffffffffu, ps, 1);
                ps += __shfl_xor_sync(0xffffffffu, ps, 2);
                l_[rh] = l_[rh] * scale + ps;
                m_[rh] = mn;
#pragma unroll
                for (int j = 0; j < 8; ++j) {
                    o[j][rh * 2]     *= scale;
                    o[j][rh * 2 + 1] *= scale;
                }
            }

            // ---- PV: 3-way split, n-interleaved MMA order ----
#pragma unroll
            for (int c = 0; c < 4; ++c) {
                uint32_t pah[4], pal[4];
#pragma unroll
                for (int half = 0; half < 2; ++half) {
                    const float* pv = s[2 * c + half];
                    __nv_bfloat16 h0, h1, h2, h3, l0, l1, l2, l3;
                    split1(pv[0], h0, l0); split1(pv[1], h1, l1);
                    split1(pv[2], h2, l2); split1(pv[3], h3, l3);
                    pah[half * 2]     = pack2(h0, h1);
                    pah[half * 2 + 1] = pack2(h2, h3);
                    pal[half * 2]     = pack2(l0, l1);
                    pal[half * 2 + 1] = pack2(l2, l3);
                }
#pragma unroll
                for (int j2 = 0; j2 < 4; ++j2) {
                    uint32_t vbh[4], vbl[4];
                    uint32_t addr = sb + 2 * (be + VH_E + (j2 * 16 + krow_l) * 72 + c * 16 + kcol_l);
                    ldsm4(vbh, addr);
                    ldsm4(vbl, addr + 2 * (VL_E - VH_E));
                    mma16816(o[2 * j2],     pah, vbh);
                    mma16816(o[2 * j2 + 1], pah, vbh + 2);
                    mma16816(o[2 * j2],     pal, vbh);
                    mma16816(o[2 * j2 + 1], pal, vbh + 2);
                    mma16816(o[2 * j2],     pah, vbl);
                    mma16816(o[2 * j2 + 1], pah, vbl + 2);
                }
            }
        }
        __syncthreads();   // all warps done with this buffer before refill
    }

    // ---- epilogue: write bf16 hi/lo att (concat-head [B,T,C]) ----
    const int b = bh >> 4;
    const int h = bh & 15;
#pragma unroll
    for (int rh = 0; rh < 2; ++rh) {
        const float inv = 1.0f / l_[rh];
        const int   row = qt * 128 + w * 16 + g + rh * 8;
#pragma unroll
        for (int j = 0; j < 8; ++j) {
            const int d = j * 8 + 2 * t4;
            float v0 = o[j][rh * 2] * inv;
            float v1 = o[j][rh * 2 + 1] * inv;
            __nv_bfloat16 h0, h1, l0, l1;
            split1(v0, h0, l0); split1(v1, h1, l1);
            size_t off = ((size_t)(b * Tn + row)) * Cn + h * 64 + d;
            *(uint32_t*)(g_ahi + off) = pack2(h0, h1);
            *(uint32_t*)(g_alo + off) = pack2(l0, l1);
        }
    }
}

// ---------------------------------------------------------------------------
extern "C" void kernel_launch(void* const* d_in, const int* in_sizes, int n_in,
                              void* d_out, int out_size)
{
    (void)in_sizes; (void)n_in; (void)out_size;
    const float* x  = (const float*)d_in[0];
    const float* Wq = (const float*)d_in[1];
    const float* Wk = (const float*)d_in[2];
    const float* Wv = (const float*)d_in[3];
    const float* Wo = (const float*)d_in[4];
    const float* bo = (const float*)d_in[5];
    float* out = (float*)d_out;

    cudaFuncSetAttribute(qkv_mma_kernel,  cudaFuncAttributeMaxDynamicSharedMemorySize, SMEM_GEMM);
    cudaFuncSetAttribute(proj_mma_kernel, cudaFuncAttributeMaxDynamicSharedMemorySize, SMEM_GEMM);
    cudaFuncSetAttribute(attn_mma_kernel, cudaFuncAttributeMaxDynamicSharedMemorySize, ATT_SMEM);

    // conversions (x and Wo)
    split_kernel<<<(Mtot * Cn / 4 + 255) / 256, 256>>>(x, Mtot * Cn / 4, 0);
    convw_kernel<<<dim3(3 * Hn, Cn / 64), 256>>>(Wq, Wk, Wv);
    split_kernel<<<(Cn * Cn / 4 + 255) / 256, 256>>>(Wo, Cn * Cn / 4, 2);

    // QKV projection -> bf16 hi/lo q,k,vt
    qkv_mma_kernel<<<dim3(Mtot / 128, 3 * Cn / 128), 256, SMEM_GEMM>>>();

    // attention (tensor cores) -> g_ahi/g_alo
    attn_mma_kernel<<<dim3(Tn / 128, Bn * Hn), 256, ATT_SMEM>>>();

    // output projection
    proj_mma_kernel<<<dim3(Mtot / 128, Cn / 128), 256, SMEM_GEMM>>>(bo, out);
}